// round 4
// baseline (speedup 1.0000x reference)
#include <cuda_runtime.h>

typedef unsigned long long ull;

#define M_    8
#define K_    256
#define DG_   128
#define D_    1024
#define HW_   1024
#define NPIX_ 32768

#define QUANT_ELEMS (33554432)
#define CODE_ELEMS  (262144)

#define GAP_THRESH 1e-3f
#define REF_WIN    2e-3f
#define CAP_       32768

// Scratch (__device__ globals per allocation rules)
__device__ float g_E[M_ * DG_ * K_];     // [m][d][k]
__device__ float g_V[M_ * K_ * DG_];     // [m][k][d]
__device__ float g_KPH[M_ * K_ * DG_];   // kproj hi [m][k][c]
__device__ float g_KPL[M_ * K_ * DG_];   // kproj lo
__device__ int   g_count;
__device__ int   g_list[CAP_];

// ---------------- packed f32x2 helpers ----------------
__device__ __forceinline__ ull pack2(float x, float y) {
    ull r; asm("mov.b64 %0, {%1,%2};" : "=l"(r) : "f"(x), "f"(y)); return r;
}
__device__ __forceinline__ void unpack2(ull v, float &x, float &y) {
    asm("mov.b64 {%0,%1}, %2;" : "=f"(x), "=f"(y) : "l"(v));
}
__device__ __forceinline__ ull fma2_(ull a, ull b, ull c) {
    ull d; asm("fma.rn.f32x2 %0, %1, %2, %3;" : "=l"(d) : "l"(a), "l"(b), "l"(c));
    return d;
}

// ---------------- double-float (Dekker) helpers: fast-math safe ----------------
struct dd { float h, l; };

__device__ __forceinline__ dd two_sum(float a, float b) {
    float s  = __fadd_rn(a, b);
    float bb = __fsub_rn(s, a);
    float e  = __fadd_rn(__fsub_rn(a, __fsub_rn(s, bb)), __fsub_rn(b, bb));
    dd r; r.h = s; r.l = e; return r;
}
__device__ __forceinline__ dd two_prod(float a, float b) {
    float p = __fmul_rn(a, b);
    float e = __fmaf_rn(a, b, -p);
    dd r; r.h = p; r.l = e; return r;
}
__device__ __forceinline__ dd dd_add(dd x, dd y) {
    dd s = two_sum(x.h, y.h);
    float lo = __fadd_rn(__fadd_rn(x.l, y.l), s.l);
    float hi = __fadd_rn(s.h, lo);
    float l  = __fadd_rn(__fsub_rn(s.h, hi), lo);
    dd r; r.h = hi; r.l = l; return r;
}
__device__ __forceinline__ dd dd_fma(dd acc, float a, float b) {
    return dd_add(acc, two_prod(a, b));
}
__device__ __forceinline__ dd dd_mul(dd x, dd y) {
    dd p = two_prod(x.h, y.h);
    float t = __fmaf_rn(x.h, y.l, p.l);
    t = __fmaf_rn(x.l, y.h, t);
    float hi = __fadd_rn(p.h, t);
    float l  = __fadd_rn(__fsub_rn(p.h, hi), t);
    dd r; r.h = hi; r.l = l; return r;
}

// ---------------------------------------------------------------------------
// Precompute (rewritten): grid (K_/8 = 32, M_), 256 threads.
// Per block: 8 k values of one m.
//   Phase A: kproj (dd) + vproj (fp32) via smem-staged wk/wv chunks.
//   Phase B: E[d][k] = sum_c kph[k][c] * wq[c][d] via smem-staged wq chunks.
// ---------------------------------------------------------------------------
#define PRE_SM_CB   0                      // [8][128]        = 1024
#define PRE_SM_KP   1024                   // [8][128]        = 1024
#define PRE_SM_WK   2048                   // [128][33]       = 4224
#define PRE_SM_WV   (2048 + 4224)          // [128][33]       = 4224
#define PRE_SM_WQ   2048                   // [32][128]       = 4096 (reuses WK region)
#define PRE_SM_FLOATS (2048 + 4224 + 4224)

__global__ void __launch_bounds__(256)
precompute_kernel(const float* __restrict__ codebook,
                  const float* __restrict__ wq,
                  const float* __restrict__ wk,
                  const float* __restrict__ wv) {
    __shared__ float sm[PRE_SM_FLOATS];
    float* cbs = sm + PRE_SM_CB;
    float* kps = sm + PRE_SM_KP;
    float* wks = sm + PRE_SM_WK;
    float* wvs = sm + PRE_SM_WV;
    float* wqs = sm + PRE_SM_WQ;

    const int m  = blockIdx.y;
    const int k0 = blockIdx.x * 8;
    const int tid   = threadIdx.x;
    const int c     = tid & 127;       // phase A: channel ; phase B: d
    const int khalf = tid >> 7;        // 0/1 -> kk in {khalf*4 .. +3}

    if (m == 0 && blockIdx.x == 0 && tid == 0) g_count = 0;

    // stage cb[8][128] (contiguous in codebook)
#pragma unroll
    for (int r = 0; r < 4; r++) {
        int idx = tid + 256 * r;
        cbs[idx] = codebook[((size_t)m * K_ + k0) * DG_ + idx];
    }

    // ---------- Phase A: kproj (dd) / vproj ----------
    dd  sk[4];
    float sv[4];
#pragma unroll
    for (int i = 0; i < 4; i++) { sk[i].h = 0.f; sk[i].l = 0.f; sv[i] = 0.f; }

    const float* wkm = wk + (size_t)m * DG_ * DG_;
    const float* wvm = wv + (size_t)m * DG_ * DG_;

    for (int dc = 0; dc < DG_; dc += 32) {
        __syncthreads();
        // stage wk/wv chunk [128 c][32 d], padded stride 33
#pragma unroll
        for (int r = 0; r < 16; r++) {
            int idx = tid + 256 * r;
            int cc = idx >> 5, j = idx & 31;
            wks[cc * 33 + j] = wkm[(size_t)cc * DG_ + dc + j];
            wvs[cc * 33 + j] = wvm[(size_t)cc * DG_ + dc + j];
        }
        __syncthreads();

#pragma unroll 4
        for (int j = 0; j < 32; j++) {
            float wkv = wks[c * 33 + j];
            float wvv = wvs[c * 33 + j];
#pragma unroll
            for (int i = 0; i < 4; i++) {
                float cbv = cbs[(khalf * 4 + i) * DG_ + dc + j];
                sk[i] = dd_fma(sk[i], cbv, wkv);
                sv[i] = fmaf(cbv, wvv, sv[i]);
            }
        }
    }

#pragma unroll
    for (int i = 0; i < 4; i++) {
        int kk = khalf * 4 + i;
        size_t gb = ((size_t)m * K_ + k0 + kk) * DG_ + c;
        g_KPH[gb] = sk[i].h;
        g_KPL[gb] = sk[i].l;
        g_V[gb]   = sv[i];
        kps[kk * DG_ + c] = sk[i].h;
    }

    // ---------- Phase B: E[d][k] ----------
    const int d = c;   // thread's output row
    float ea[4];
#pragma unroll
    for (int i = 0; i < 4; i++) ea[i] = 0.f;

    const float* wqm = wq + (size_t)m * DG_ * DG_;
    for (int c0 = 0; c0 < DG_; c0 += 32) {
        __syncthreads();
        // stage wq chunk [32 c][128 d] (row-contiguous, no pad needed)
#pragma unroll
        for (int r = 0; r < 16; r++) {
            int idx = tid + 256 * r;
            wqs[idx] = wqm[(size_t)c0 * DG_ + idx];
        }
        __syncthreads();

#pragma unroll 4
        for (int cc = 0; cc < 32; cc++) {
            float wv_ = wqs[cc * DG_ + d];     // lane-stride 1, conflict-free
#pragma unroll
            for (int i = 0; i < 4; i++)
                ea[i] = fmaf(kps[(khalf * 4 + i) * DG_ + c0 + cc], wv_, ea[i]);
        }
    }

#pragma unroll
    for (int i = 0; i < 4; i++)
        g_E[((size_t)m * DG_ + d) * K_ + k0 + khalf * 4 + i] = ea[i];
}

// ---------------------------------------------------------------------------
// Main kernel: block = 256 threads, tile = 64 pixels x 256 k, fixed m.
// grid (NPIX_/64 = 512, M_ = 8)
// Thread kt owns k in {kt*4..kt*4+3} and {128+kt*4..+3}  (conflict-free LDS)
// ---------------------------------------------------------------------------
#define PIX  64
#define DCH  16
#define KCH  32

#define SM_QS    0
#define SM_ES    1024
#define SM_SS    5120
#define SM_RINV  (5120 + 16448)
#define SM_VS    (5120 + 16448 + 64)
#define SM_FLOATS (5120 + 16448 + 64 + 4096)
#define SMEM_BYTES (SM_FLOATS * 4)

__global__ void __launch_bounds__(256, 2)
main_kernel(const float* __restrict__ latent,
            const float* __restrict__ unif,
            float* __restrict__ quant_out,
            float* __restrict__ code_out,
            float* __restrict__ logit_out) {
    extern __shared__ float sm[];
    float* Qs    = sm + SM_QS;
    float* Es    = sm + SM_ES;
    float* Ss    = sm + SM_SS;
    float* rinvs = sm + SM_RINV;
    float* Vs    = sm + SM_VS;

    const int m  = blockIdx.y;
    const int p0 = blockIdx.x * PIX;
    const int n  = p0 >> 10;
    const int s0 = p0 & 1023;
    const int tid = threadIdx.x;
    const int kt  = tid & 31;
    const int pt  = tid >> 5;

    const float* latb = latent + ((size_t)n * D_ + (size_t)m * DG_) * HW_ + s0;
    const float* Em   = g_E + (size_t)m * DG_ * K_;

    // ---------------- Pass 1: logits ----------------
    ull acc[8][4];
#pragma unroll
    for (int i = 0; i < 8; i++)
#pragma unroll
        for (int jj = 0; jj < 4; jj++) acc[i][jj] = 0ull;

    for (int d0 = 0; d0 < DG_; d0 += DCH) {
#pragma unroll
        for (int r = 0; r < 4; r++) {
            int idx = tid + 256 * r;
            int dr = idx >> 6, cc = idx & 63;
            Qs[idx] = latb[(size_t)(d0 + dr) * HW_ + cc];
        }
#pragma unroll
        for (int r = 0; r < 16; r++) {
            int idx = tid + 256 * r;
            Es[idx] = Em[(size_t)d0 * K_ + idx];
        }
        __syncthreads();

#pragma unroll
        for (int d = 0; d < DCH; d++) {
            // k = kt*4..+3 (low half) and 128+kt*4..+3 (high half): 16B lane
            // stride -> each LDS.128 phase covers exactly 128B, conflict-free.
            float4 e0 = *(const float4*)&Es[d * K_ + kt * 4];
            float4 e1 = *(const float4*)&Es[d * K_ + 128 + kt * 4];
            ull eb[4];
            eb[0] = pack2(e0.x, e0.y); eb[1] = pack2(e0.z, e0.w);
            eb[2] = pack2(e1.x, e1.y); eb[3] = pack2(e1.z, e1.w);
            float4 q0 = *(const float4*)&Qs[d * PIX + pt * 8];      // warp broadcast
            float4 q1 = *(const float4*)&Qs[d * PIX + pt * 8 + 4];  // warp broadcast
            float qv[8] = {q0.x, q0.y, q0.z, q0.w, q1.x, q1.y, q1.z, q1.w};
#pragma unroll
            for (int i = 0; i < 8; i++) {
                ull qd = pack2(qv[i], qv[i]);
#pragma unroll
                for (int jj = 0; jj < 4; jj++)
                    acc[i][jj] = fma2_(qd, eb[jj], acc[i][jj]);
            }
        }
        __syncthreads();
    }

    // ---------------- Epilogue ----------------
#pragma unroll 2
    for (int i = 0; i < 8; i++) {
        const int p = pt * 8 + i;
        const size_t pg = (size_t)(p0 + p);

        float l[8];     // l[0..3] -> k = kt*4+j ; l[4..7] -> k = 128+kt*4+(j-4)
#pragma unroll
        for (int jj = 0; jj < 4; jj++) unpack2(acc[i][jj], l[2 * jj], l[2 * jj + 1]);

        float* lo = logit_out + (pg * M_ + m) * K_;
        *(float4*)(lo + kt * 4)       = make_float4(l[0], l[1], l[2], l[3]);
        *(float4*)(lo + 128 + kt * 4) = make_float4(l[4], l[5], l[6], l[7]);

        // top-2 of raw logits (first-index tie break on top-1)
        float b1 = l[0]; int i1 = kt * 4; float b2 = -3.4e38f;
#pragma unroll
        for (int j = 1; j < 8; j++) {
            int kj = (j < 4) ? (kt * 4 + j) : (128 + kt * 4 + j - 4);
            if (l[j] > b1 || (l[j] == b1 && kj < i1)) { b2 = b1; b1 = l[j]; i1 = kj; }
            else if (l[j] > b2) b2 = l[j];
        }
#pragma unroll
        for (int o = 16; o > 0; o >>= 1) {
            float ob1 = __shfl_xor_sync(0xFFFFFFFFu, b1, o);
            int   oi1 = __shfl_xor_sync(0xFFFFFFFFu, i1, o);
            float ob2 = __shfl_xor_sync(0xFFFFFFFFu, b2, o);
            if (ob1 > b1 || (ob1 == b1 && oi1 < i1)) {
                b2 = fmaxf(b1, ob2); b1 = ob1; i1 = oi1;
            } else {
                b2 = fmaxf(b2, ob1);
            }
        }

        // gumbel: -log(-log u); inner log via log1pf (accurate at u->1)
        const float* up = unif + (pg * M_ + m) * K_;
        float4 u0 = *(const float4*)(up + kt * 4);
        float4 u1 = *(const float4*)(up + 128 + kt * 4);
        float uu[8] = {u0.x, u0.y, u0.z, u0.w, u1.x, u1.y, u1.z, u1.w};
        float t[8];
#pragma unroll
        for (int j = 0; j < 8; j++) {
            float nlu = -log1pf(__fsub_rn(uu[j], 1.0f));
            t[j] = l[j] - __logf(nlu);
        }

        float tm = t[0];
#pragma unroll
        for (int j = 1; j < 8; j++) tm = fmaxf(tm, t[j]);
#pragma unroll
        for (int o = 16; o > 0; o >>= 1)
            tm = fmaxf(tm, __shfl_xor_sync(0xFFFFFFFFu, tm, o));

        float e[8], s = 0.f;
#pragma unroll
        for (int j = 0; j < 8; j++) { e[j] = __expf(t[j] - tm); s += e[j]; }
#pragma unroll
        for (int o = 16; o > 0; o >>= 1)
            s += __shfl_xor_sync(0xFFFFFFFFu, s, o);

#pragma unroll
        for (int j = 0; j < 4; j++) Ss[p * 257 + kt * 4 + j] = e[j];
#pragma unroll
        for (int j = 4; j < 8; j++) Ss[p * 257 + 128 + kt * 4 + j - 4] = e[j];
        if (kt == 0) {
            rinvs[p] = 1.0f / s;
            code_out[pg * M_ + m] = (float)i1;
            if (b1 - b2 < GAP_THRESH) {
                int idx = atomicAdd(&g_count, 1);
                if (idx < CAP_) g_list[idx] = (int)(pg * M_ + m);
            }
        }
    }

    // ---------------- Pass 2: quantized ----------------
    const int pl    = tid & 63;
    const int dbase = (tid >> 6) * 32;

    ull qacc[16];
#pragma unroll
    for (int jj = 0; jj < 16; jj++) qacc[jj] = 0ull;

    const float* Vm = g_V + (size_t)m * K_ * DG_;
    for (int k0 = 0; k0 < K_; k0 += KCH) {
        __syncthreads();
#pragma unroll
        for (int r = 0; r < 16; r++) {
            int idx = tid + 256 * r;
            Vs[idx] = Vm[(size_t)k0 * DG_ + idx];
        }
        __syncthreads();

#pragma unroll 4
        for (int kk = 0; kk < KCH; kk++) {
            float svl = Ss[pl * 257 + k0 + kk];
            ull sp = pack2(svl, svl);
#pragma unroll
            for (int jj = 0; jj < 8; jj++) {
                float4 v = *(const float4*)&Vs[kk * DG_ + dbase + jj * 4];
                qacc[2 * jj]     = fma2_(sp, pack2(v.x, v.y), qacc[2 * jj]);
                qacc[2 * jj + 1] = fma2_(sp, pack2(v.z, v.w), qacc[2 * jj + 1]);
            }
        }
    }

    float ri = rinvs[pl];
    float* qb = quant_out + ((size_t)n * D_ + (size_t)m * DG_ + dbase) * HW_ + s0 + pl;
#pragma unroll
    for (int jj = 0; jj < 16; jj++) {
        float x, y; unpack2(qacc[jj], x, y);
        qb[(size_t)(2 * jj) * HW_]     = x * ri;
        qb[(size_t)(2 * jj + 1) * HW_] = y * ri;
    }
}

// ---------------------------------------------------------------------------
// Refine: near-exact argmax for flagged near-tie pixels. One warp per entry.
// ---------------------------------------------------------------------------
__global__ void __launch_bounds__(128)
refine_kernel(const float* __restrict__ latent,
              const float* __restrict__ wq,
              const float* __restrict__ logit_out,
              float* __restrict__ code_out) {
    __shared__ float qv_s[4][DG_];
    __shared__ float qh_s[4][DG_];
    __shared__ float ql_s[4][DG_];

    const int wid  = threadIdx.x >> 5;
    const int lane = threadIdx.x & 31;
    const int gw   = blockIdx.x * 4 + wid;
    const int tw   = gridDim.x * 4;

    int cnt = g_count;
    if (cnt > CAP_) cnt = CAP_;

    for (int e = gw; e < cnt; e += tw) {
        int ent = g_list[e];
        int m = ent & 7;
        int pg = ent >> 3;
        int n = pg >> 10, s = pg & 1023;

        const float* latb = latent + ((size_t)n * D_ + (size_t)m * DG_) * HW_ + s;
        for (int d = lane; d < DG_; d += 32) qv_s[wid][d] = latb[(size_t)d * HW_];
        __syncwarp();

        const float* wqm = wq + (size_t)m * DG_ * DG_;
#pragma unroll
        for (int ci = 0; ci < 4; ci++) {
            int c = lane + 32 * ci;
            const float* wr = wqm + (size_t)c * DG_;
            dd a; a.h = 0.f; a.l = 0.f;
            for (int d = 0; d < DG_; d++) a = dd_fma(a, qv_s[wid][d], wr[d]);
            qh_s[wid][c] = a.h; ql_s[wid][c] = a.l;
        }
        __syncwarp();

        const float* lo = logit_out + ((size_t)pg * M_ + m) * K_;
        float l[8]; float fm = -3.4e38f;
#pragma unroll
        for (int j = 0; j < 8; j++) { l[j] = lo[lane * 8 + j]; fm = fmaxf(fm, l[j]); }
#pragma unroll
        for (int o = 16; o > 0; o >>= 1)
            fm = fmaxf(fm, __shfl_xor_sync(0xFFFFFFFFu, fm, o));
        float thresh = fm - REF_WIN;

        double bestv = -1e300; int besti = 1 << 30;
        const float* kph = g_KPH + ((size_t)m * K_) * DG_;
        const float* kpl = g_KPL + ((size_t)m * K_) * DG_;

#pragma unroll
        for (int j = 0; j < 8; j++) {
            unsigned b = __ballot_sync(0xFFFFFFFFu, l[j] >= thresh);
            while (b) {
                int src = __ffs(b) - 1; b &= b - 1;
                int k = src * 8 + j;
                const float* kh = kph + (size_t)k * DG_;
                const float* kl = kpl + (size_t)k * DG_;
                dd a; a.h = 0.f; a.l = 0.f;
#pragma unroll
                for (int ci = 0; ci < 4; ci++) {
                    int c = lane + 32 * ci;
                    dd kp; kp.h = kh[c]; kp.l = kl[c];
                    dd qp; qp.h = qh_s[wid][c]; qp.l = ql_s[wid][c];
                    a = dd_add(a, dd_mul(kp, qp));
                }
                double v = (double)a.h + (double)a.l;
#pragma unroll
                for (int o = 16; o > 0; o >>= 1)
                    v += __shfl_xor_sync(0xFFFFFFFFu, v, o);
                if (v > bestv || (v == bestv && k < besti)) { bestv = v; besti = k; }
            }
        }
        if (lane == 0) code_out[(size_t)pg * M_ + m] = (float)besti;
    }
}

// ---------------------------------------------------------------------------
extern "C" void kernel_launch(void* const* d_in, const int* in_sizes, int n_in,
                              void* d_out, int out_size) {
    const float* latent   = (const float*)d_in[0];
    const float* codebook = (const float*)d_in[1];
    const float* wq       = (const float*)d_in[2];
    const float* wk       = (const float*)d_in[3];
    const float* wv       = (const float*)d_in[4];
    const float* unif     = (const float*)d_in[5];

    float* out   = (float*)d_out;
    float* quant = out;
    float* code  = out + QUANT_ELEMS;
    float* logit = out + QUANT_ELEMS + CODE_ELEMS;

    precompute_kernel<<<dim3(K_ / 8, M_), 256>>>(codebook, wq, wk, wv);

    cudaFuncSetAttribute(main_kernel,
                         cudaFuncAttributeMaxDynamicSharedMemorySize, SMEM_BYTES);
    main_kernel<<<dim3(NPIX_ / PIX, M_), 256, SMEM_BYTES>>>(
        latent, unif, quant, code, logit);

    refine_kernel<<<64, 128>>>(latent, wq, logit, code);
}

// round 6
// speedup vs baseline: 1.3273x; 1.3273x over previous
#include <cuda_runtime.h>
#include <cuda_bf16.h>
#include <cstdint>

#define M_    8
#define K_    256
#define DG_   128
#define D_    1024
#define HW_   1024
#define NPIX_ 32768
#define QUANT_ELEMS 33554432
#define CODE_ELEMS  262144
#define GAP_THRESH 1e-3f
#define REF_WIN    2e-3f
#define CAP_       32768

__device__ unsigned short g_Ebh[M_ * K_ * DG_];  // E [m][k][d] bf16 hi
__device__ unsigned short g_Ebl[M_ * K_ * DG_];
__device__ unsigned short g_Vth[M_ * DG_ * K_];  // Vt [m][d][k] bf16 hi
__device__ unsigned short g_Vtl[M_ * DG_ * K_];
__device__ float g_KPH[M_ * K_ * DG_];
__device__ float g_KPL[M_ * K_ * DG_];
__device__ int   g_count;
__device__ int   g_list[CAP_];

__device__ __forceinline__ uint32_t smem_to_u32(const void* p) {
    uint32_t a;
    asm("{ .reg .u64 t; cvta.to.shared.u64 t, %1; cvt.u32.u64 %0, t; }" : "=r"(a) : "l"(p));
    return a;
}
__device__ __forceinline__ void ldsm4(uint32_t* r, uint32_t addr) {
    asm volatile("ldmatrix.sync.aligned.m8n8.x4.shared.b16 {%0,%1,%2,%3}, [%4];"
        : "=r"(r[0]), "=r"(r[1]), "=r"(r[2]), "=r"(r[3]) : "r"(addr));
}
__device__ __forceinline__ void mma_bf16(float* d, const uint32_t* a, const uint32_t* b) {
    asm volatile("mma.sync.aligned.m16n8k16.row.col.f32.bf16.bf16.f32 "
        "{%0,%1,%2,%3}, {%4,%5,%6,%7}, {%8,%9}, {%0,%1,%2,%3};"
        : "+f"(d[0]), "+f"(d[1]), "+f"(d[2]), "+f"(d[3])
        : "r"(a[0]), "r"(a[1]), "r"(a[2]), "r"(a[3]), "r"(b[0]), "r"(b[1]));
}

struct dd { float h, l; };
__device__ __forceinline__ dd two_sum(float a, float b) {
    float s = __fadd_rn(a, b), bb = __fsub_rn(s, a);
    float e = __fadd_rn(__fsub_rn(a, __fsub_rn(s, bb)), __fsub_rn(b, bb));
    dd r; r.h = s; r.l = e; return r;
}
__device__ __forceinline__ dd two_prod(float a, float b) {
    float p = __fmul_rn(a, b), e = __fmaf_rn(a, b, -p);
    dd r; r.h = p; r.l = e; return r;
}
__device__ __forceinline__ dd dd_add(dd x, dd y) {
    dd s = two_sum(x.h, y.h);
    float lo = __fadd_rn(__fadd_rn(x.l, y.l), s.l);
    float hi = __fadd_rn(s.h, lo);
    float l = __fadd_rn(__fsub_rn(s.h, hi), lo);
    dd r; r.h = hi; r.l = l; return r;
}
__device__ __forceinline__ dd dd_fma(dd a, float x, float y) { return dd_add(a, two_prod(x, y)); }
__device__ __forceinline__ dd dd_mul(dd x, dd y) {
    dd p = two_prod(x.h, y.h);
    float t = __fmaf_rn(x.h, y.l, p.l); t = __fmaf_rn(x.l, y.h, t);
    float hi = __fadd_rn(p.h, t), l = __fadd_rn(__fsub_rn(p.h, hi), t);
    dd r; r.h = hi; r.l = l; return r;
}
__device__ __forceinline__ void bf16_split(float v, unsigned short &h, unsigned short &l) {
    __nv_bfloat16 bh = __float2bfloat16(v);
    float hf = __bfloat162float(bh);
    h = __bfloat16_as_ushort(bh);
    l = __bfloat16_as_ushort(__float2bfloat16(v - hf));
}
__device__ __forceinline__ float neglog_acc(float u) {
    float t = __fsub_rn(u, 1.0f);
    float p = fmaf(t, 0.142857143f, -0.166666667f);
    p = fmaf(t, p, 0.2f); p = fmaf(t, p, -0.25f);
    p = fmaf(t, p, 0.333333333f); p = fmaf(t, p, -0.5f); p = fmaf(t, p, 1.0f);
    return (u > 0.75f) ? -(t * p) : -__logf(u);
}

// ---------------- precompute: kproj(dd), Vt/E bf16 splits ----------------
#define P_CB 0
#define P_KP 1024
#define P_WK 2048
#define P_WV (2048 + 4224)
#define P_WQ 2048
#define P_FLOATS (2048 + 4224 + 4224)

__global__ void __launch_bounds__(256)
precompute_kernel(const float* __restrict__ codebook, const float* __restrict__ wq,
                  const float* __restrict__ wk, const float* __restrict__ wv) {
    __shared__ float sm[P_FLOATS];
    float *cbs = sm + P_CB, *kps = sm + P_KP, *wks = sm + P_WK, *wvs = sm + P_WV, *wqs = sm + P_WQ;
    const int m = blockIdx.y, k0 = blockIdx.x * 8, tid = threadIdx.x;
    const int c = tid & 127, khalf = tid >> 7;
    if (m == 0 && blockIdx.x == 0 && tid == 0) g_count = 0;
#pragma unroll
    for (int r = 0; r < 4; r++) {
        int idx = tid + 256 * r;
        cbs[idx] = codebook[((size_t)m * K_ + k0) * DG_ + idx];
    }
    dd sk[4]; float sv[4];
#pragma unroll
    for (int i = 0; i < 4; i++) { sk[i].h = sk[i].l = 0.f; sv[i] = 0.f; }
    const float* wkm = wk + (size_t)m * DG_ * DG_;
    const float* wvm = wv + (size_t)m * DG_ * DG_;
    for (int dc = 0; dc < DG_; dc += 32) {
        __syncthreads();
#pragma unroll
        for (int r = 0; r < 16; r++) {
            int idx = tid + 256 * r, cc = idx >> 5, j = idx & 31;
            wks[cc * 33 + j] = wkm[(size_t)cc * DG_ + dc + j];
            wvs[cc * 33 + j] = wvm[(size_t)cc * DG_ + dc + j];
        }
        __syncthreads();
#pragma unroll 4
        for (int j = 0; j < 32; j++) {
            float wkv = wks[c * 33 + j], wvv = wvs[c * 33 + j];
#pragma unroll
            for (int i = 0; i < 4; i++) {
                float cbv = cbs[(khalf * 4 + i) * DG_ + dc + j];
                sk[i] = dd_fma(sk[i], cbv, wkv);
                sv[i] = fmaf(cbv, wvv, sv[i]);
            }
        }
    }
#pragma unroll
    for (int i = 0; i < 4; i++) {
        int kk = k0 + khalf * 4 + i;
        size_t gb = ((size_t)m * K_ + kk) * DG_ + c;
        g_KPH[gb] = sk[i].h; g_KPL[gb] = sk[i].l;
        unsigned short vh, vl; bf16_split(sv[i], vh, vl);
        size_t vt = ((size_t)m * DG_ + c) * K_ + kk;
        g_Vth[vt] = vh; g_Vtl[vt] = vl;
        kps[(khalf * 4 + i) * DG_ + c] = sk[i].h;
    }
    const int d = c;
    float ea[4] = {0.f, 0.f, 0.f, 0.f};
    const float* wqm = wq + (size_t)m * DG_ * DG_;
    for (int c0 = 0; c0 < DG_; c0 += 32) {
        __syncthreads();
#pragma unroll
        for (int r = 0; r < 16; r++) {
            int idx = tid + 256 * r;
            wqs[idx] = wqm[(size_t)c0 * DG_ + idx];
        }
        __syncthreads();
#pragma unroll 4
        for (int cc = 0; cc < 32; cc++) {
            float wv_ = wqs[cc * DG_ + d];
#pragma unroll
            for (int i = 0; i < 4; i++)
                ea[i] = fmaf(kps[(khalf * 4 + i) * DG_ + c0 + cc], wv_, ea[i]);
        }
    }
#pragma unroll
    for (int i = 0; i < 4; i++) {
        int kk = k0 + khalf * 4 + i;
        unsigned short eh, el; bf16_split(ea[i], eh, el);
        size_t eb = ((size_t)m * K_ + kk) * DG_ + d;
        g_Ebh[eb] = eh; g_Ebl[eb] = el;
    }
}

// ---------------- main mma.sync kernel: 64 pix x fixed m ----------------
// smem byte offsets
#define SM_B1S 0
#define SM_B2S 512
#define SM_I1S 1024
#define SM_SUMS 1536
#define SM_RI  2048
#define SM_STAGE 4096
#define SM_AH (SM_STAGE)
#define SM_AL (SM_STAGE + 5120)
#define SM_EH (SM_STAGE + 10240)
#define SM_EL (SM_STAGE + 30720)
#define SM_VH0 (SM_STAGE)
#define SM_VL0 (SM_STAGE + 10240)
#define SM_VH1 (SM_STAGE + 20480)
#define SM_VL1 (SM_STAGE + 30720)
#define SM_QB  (SM_STAGE)
#define SMEM_TOTAL (4096 + 51200)

#define UPD(b1, b2, i1, v, k) do { \
    if ((v) > (b1)) { b2 = b1; b1 = (v); i1 = (k); } \
    else if ((v) > (b2)) b2 = (v); } while (0)

__global__ void __launch_bounds__(256, 1)
main_kernel(const float* __restrict__ latent, const float* __restrict__ unif,
            float* __restrict__ quant_out, float* __restrict__ code_out,
            float* __restrict__ logit_out) {
    extern __shared__ char smem[];
    const uint32_t sb = smem_to_u32(smem);
    const int m = blockIdx.y, p0 = blockIdx.x * 64;
    const int n = p0 >> 10, s0 = p0 & 1023;
    const int tid = threadIdx.x, w = tid >> 5, lane = tid & 31;
    const int wp = w >> 1, wk = w & 1;
    const int gid = lane >> 2, tig = lane & 3;
    const int li = lane & 7, lg = lane >> 3;

    float* b1s = (float*)(smem + SM_B1S);
    float* b2s = (float*)(smem + SM_B2S);
    int*   i1s = (int*)(smem + SM_I1S);
    float* sums = (float*)(smem + SM_SUMS);
    float* rinv = (float*)(smem + SM_RI);
    float* qbuf = (float*)(smem + SM_QB);

    // ldmatrix per-lane address components
    const int a_row = wp * 16 + ((lg & 1) << 3) + li;   // A: m-rows, groups 0/2 low, 1/3 high
    const int a_col = ((lg >> 1) << 3);                 // A: k-cols, groups 0/1 low, 2/3 high
    const int b_row = ((lg >> 1) << 3) + li;            // B: n-rows
    const int b_col = ((lg & 1) << 3);                  // B: k-cols
    const uint32_t aAh = sb + SM_AH + a_row * 80 + a_col * 2;
    const uint32_t aAl = sb + SM_AL + a_row * 80 + a_col * 2;
    const uint32_t aEh = sb + SM_EH + (wk * 128 + b_row) * 80 + b_col * 2;
    const uint32_t aEl = sb + SM_EL + (wk * 128 + b_row) * 80 + b_col * 2;

    const float* latb = latent + ((size_t)n * D_ + (size_t)m * DG_) * HW_ + s0;
    const uint4* ebH = (const uint4*)(g_Ebh + (size_t)m * K_ * DG_);
    const uint4* ebL = (const uint4*)(g_Ebl + (size_t)m * K_ * DG_);

    // ================= GEMM1: logits[64 pix][256 k] =================
    float acc[16][4];
#pragma unroll
    for (int i = 0; i < 16; i++)
#pragma unroll
        for (int j = 0; j < 4; j++) acc[i][j] = 0.f;

    for (int c4 = 0; c4 < 4; c4++) {          // d chunk of 32
        // stage A [64 pix][32 d] bf16 hi/lo, 80B rows
#pragma unroll
        for (int j = 0; j < 4; j++) {
            int dp = (tid >> 6) + 4 * j;      // d-pair 0..15
            int pix = tid & 63;
            float f0 = latb[(size_t)(32 * c4 + 2 * dp) * HW_ + pix];
            float f1 = latb[(size_t)(32 * c4 + 2 * dp + 1) * HW_ + pix];
            unsigned short h0, l0, h1, l1;
            bf16_split(f0, h0, l0); bf16_split(f1, h1, l1);
            *(uint32_t*)(smem + SM_AH + pix * 80 + dp * 4) = ((uint32_t)h1 << 16) | h0;
            *(uint32_t*)(smem + SM_AL + pix * 80 + dp * 4) = ((uint32_t)l1 << 16) | l0;
        }
        // stage E [256 k][32 d] bf16 hi/lo
#pragma unroll
        for (int j = 0; j < 4; j++) {
            int q = tid + 256 * j, kR = q >> 2, dc = q & 3;
            size_t si = (size_t)kR * 16 + c4 * 4 + dc;
            *(uint4*)(smem + SM_EH + kR * 80 + dc * 16) = ebH[si];
            *(uint4*)(smem + SM_EL + kR * 80 + dc * 16) = ebL[si];
        }
        __syncthreads();
#pragma unroll
        for (int s = 0; s < 2; s++) {
            uint32_t ah[4], al[4];
            ldsm4(ah, aAh + s * 32);
            ldsm4(al, aAl + s * 32);
#pragma unroll
            for (int nf2 = 0; nf2 < 8; nf2++) {
                uint32_t bh[4], bl[4];
                ldsm4(bh, aEh + nf2 * 1280 + s * 32);
                ldsm4(bl, aEl + nf2 * 1280 + s * 32);
                mma_bf16(acc[2 * nf2], ah, bh);
                mma_bf16(acc[2 * nf2], ah, bl);
                mma_bf16(acc[2 * nf2], al, bh);
                mma_bf16(acc[2 * nf2 + 1], ah, bh + 2);
                mma_bf16(acc[2 * nf2 + 1], ah, bl + 2);
                mma_bf16(acc[2 * nf2 + 1], al, bh + 2);
            }
        }
        __syncthreads();
    }

    // ================= Epilogue: logits out, gumbel-softmax, S frags =================
    const int p_r = wp * 16 + gid;
    const size_t pgA = (size_t)(p0 + p_r), pgB = pgA + 8;
    float* lpA = logit_out + (pgA * M_ + m) * K_ + wk * 128 + 2 * tig;
    float* lpB = logit_out + (pgB * M_ + m) * K_ + wk * 128 + 2 * tig;
    const float* upA = unif + (pgA * M_ + m) * K_ + wk * 128 + 2 * tig;
    const float* upB = unif + (pgB * M_ + m) * K_ + wk * 128 + 2 * tig;

    float b1r[2] = {-3.4e38f, -3.4e38f}, b2r[2] = {-3.4e38f, -3.4e38f};
    int i1r[2] = {0, 0};
    float sumr[2] = {0.f, 0.f};
    uint32_t sfh[8][4], sfl[8][4];

#pragma unroll
    for (int nf = 0; nf < 16; nf++) {
        int kk = wk * 128 + nf * 8 + 2 * tig;
        float l00 = acc[nf][0], l01 = acc[nf][1], l10 = acc[nf][2], l11 = acc[nf][3];
        *(float2*)(lpA + nf * 8) = make_float2(l00, l01);
        *(float2*)(lpB + nf * 8) = make_float2(l10, l11);
        float2 u0 = *(const float2*)(upA + nf * 8);
        float2 u1 = *(const float2*)(upB + nf * 8);
        UPD(b1r[0], b2r[0], i1r[0], l00, kk);
        UPD(b1r[0], b2r[0], i1r[0], l01, kk + 1);
        UPD(b1r[1], b2r[1], i1r[1], l10, kk);
        UPD(b1r[1], b2r[1], i1r[1], l11, kk + 1);
        float e00 = __expf(l00 - __logf(neglog_acc(u0.x)));
        float e01 = __expf(l01 - __logf(neglog_acc(u0.y)));
        float e10 = __expf(l10 - __logf(neglog_acc(u1.x)));
        float e11 = __expf(l11 - __logf(neglog_acc(u1.y)));
        sumr[0] += e00 + e01;
        sumr[1] += e10 + e11;
        unsigned short h00, lo00, h01, lo01, h10, lo10, h11, lo11;
        bf16_split(e00, h00, lo00); bf16_split(e01, h01, lo01);
        bf16_split(e10, h10, lo10); bf16_split(e11, h11, lo11);
        int s = nf >> 1, off = (nf & 1) * 2;
        sfh[s][off]     = ((uint32_t)h01 << 16) | h00;
        sfh[s][off + 1] = ((uint32_t)h11 << 16) | h10;
        sfl[s][off]     = ((uint32_t)lo01 << 16) | lo00;
        sfl[s][off + 1] = ((uint32_t)lo11 << 16) | lo10;
    }
#pragma unroll
    for (int r = 0; r < 2; r++) {
#pragma unroll
        for (int o = 1; o <= 2; o <<= 1) {
            float ob1 = __shfl_xor_sync(0xFFFFFFFFu, b1r[r], o);
            int   oi1 = __shfl_xor_sync(0xFFFFFFFFu, i1r[r], o);
            float ob2 = __shfl_xor_sync(0xFFFFFFFFu, b2r[r], o);
            if (ob1 > b1r[r] || (ob1 == b1r[r] && oi1 < i1r[r])) {
                b2r[r] = fmaxf(b1r[r], ob2); b1r[r] = ob1; i1r[r] = oi1;
            } else b2r[r] = fmaxf(b2r[r], ob1);
            sumr[r] += __shfl_xor_sync(0xFFFFFFFFu, sumr[r], o);
        }
    }
    if (tig == 0) {
        b1s[wk * 64 + p_r] = b1r[0];  b1s[wk * 64 + p_r + 8] = b1r[1];
        b2s[wk * 64 + p_r] = b2r[0];  b2s[wk * 64 + p_r + 8] = b2r[1];
        i1s[wk * 64 + p_r] = i1r[0];  i1s[wk * 64 + p_r + 8] = i1r[1];
        sums[wk * 64 + p_r] = sumr[0]; sums[wk * 64 + p_r + 8] = sumr[1];
    }
    __syncthreads();

    if (tid < 64) {
        const int p = tid;
        const size_t pg = (size_t)(p0 + p);
        float a1 = b1s[p], a2 = b2s[p];           int ai = i1s[p];
        float c1 = b1s[64 + p], c2 = b2s[64 + p]; int ci = i1s[64 + p];
        float b1, b2; int i1;
        if (a1 >= c1) { b1 = a1; i1 = ai; b2 = fmaxf(a2, fmaxf(c1, c2)); }
        else          { b1 = c1; i1 = ci; b2 = fmaxf(c2, fmaxf(a1, a2)); }
        rinv[p] = 1.0f / (sums[p] + sums[64 + p]);
        code_out[pg * M_ + m] = (float)i1;
        if (b1 - b2 < GAP_THRESH) {
            int idx = atomicAdd(&g_count, 1);
            if (idx < CAP_) g_list[idx] = (int)(pg * M_ + m);
        }
    }

    // ================= GEMM2: quant[64 pix][128 d] = S x Vt^T =================
    float acc2[16][4];
#pragma unroll
    for (int i = 0; i < 16; i++)
#pragma unroll
        for (int j = 0; j < 4; j++) acc2[i][j] = 0.f;

    const uint4* vtH = (const uint4*)(g_Vth + (size_t)m * DG_ * K_);
    const uint4* vtL = (const uint4*)(g_Vtl + (size_t)m * DG_ * K_);
    const uint32_t bvh = sb + (wk ? SM_VH1 : SM_VH0) + b_row * 80 + b_col * 2;
    const uint32_t bvl = sb + (wk ? SM_VL1 : SM_VL0) + b_row * 80 + b_col * 2;

    for (int it = 0; it < 4; it++) {          // k chunk of 32 per half
        __syncthreads();
#pragma unroll
        for (int jj = 0; jj < 2; jj++) {
            int q = tid + 256 * jj, dR = q >> 2, kc = q & 3;
            size_t si = (size_t)dR * 32 + it * 4 + kc;
            *(uint4*)(smem + SM_VH0 + dR * 80 + kc * 16) = vtH[si];
            *(uint4*)(smem + SM_VL0 + dR * 80 + kc * 16) = vtL[si];
            *(uint4*)(smem + SM_VH1 + dR * 80 + kc * 16) = vtH[si + 16];
            *(uint4*)(smem + SM_VL1 + dR * 80 + kc * 16) = vtL[si + 16];
        }
        __syncthreads();
#pragma unroll
        for (int s = 0; s < 2; s++) {
            const int sk = it * 2 + s;
#pragma unroll
            for (int nf2 = 0; nf2 < 8; nf2++) {
                uint32_t bh[4], bl[4];
                ldsm4(bh, bvh + nf2 * 1280 + s * 32);
                ldsm4(bl, bvl + nf2 * 1280 + s * 32);
                mma_bf16(acc2[2 * nf2], sfh[sk], bh);
                mma_bf16(acc2[2 * nf2], sfh[sk], bl);
                mma_bf16(acc2[2 * nf2], sfl[sk], bh);
                mma_bf16(acc2[2 * nf2 + 1], sfh[sk], bh + 2);
                mma_bf16(acc2[2 * nf2 + 1], sfh[sk], bl + 2);
                mma_bf16(acc2[2 * nf2 + 1], sfl[sk], bh + 2);
            }
        }
    }
    __syncthreads();   // Vt buffers free; qbuf reuses region

    // combine k-half partials in smem [64 pix][129]
    if (wk == 0) {
#pragma unroll
        for (int nf = 0; nf < 16; nf++) {
            int d = 8 * nf + 2 * tig;
            qbuf[p_r * 129 + d]       = acc2[nf][0];
            qbuf[p_r * 129 + d + 1]   = acc2[nf][1];
            qbuf[(p_r + 8) * 129 + d]     = acc2[nf][2];
            qbuf[(p_r + 8) * 129 + d + 1] = acc2[nf][3];
        }
    }
    __syncthreads();
    if (wk == 1) {
#pragma unroll
        for (int nf = 0; nf < 16; nf++) {
            int d = 8 * nf + 2 * tig;
            qbuf[p_r * 129 + d]       += acc2[nf][0];
            qbuf[p_r * 129 + d + 1]   += acc2[nf][1];
            qbuf[(p_r + 8) * 129 + d]     += acc2[nf][2];
            qbuf[(p_r + 8) * 129 + d + 1] += acc2[nf][3];
        }
    }
    __syncthreads();

    // readout: scale by rinv, coalesced stores
    {
        const int pix = tid & 63, dg2 = tid >> 6;
        const float ri = rinv[pix];
        float* qb = quant_out + ((size_t)n * D_ + (size_t)m * DG_) * HW_ + s0 + pix;
#pragma unroll
        for (int j = 0; j < 32; j++) {
            int d = dg2 * 32 + j;
            qb[(size_t)d * HW_] = qbuf[pix * 129 + d] * ri;
        }
    }
}

// ---------------- refine: dd-exact argmax for near-tie pixels ----------------
__global__ void __launch_bounds__(128)
refine_kernel(const float* __restrict__ latent, const float* __restrict__ wq,
              const float* __restrict__ logit_out, float* __restrict__ code_out) {
    __shared__ float qv_s[4][DG_], qh_s[4][DG_], ql_s[4][DG_];
    const int wid = threadIdx.x >> 5, lane = threadIdx.x & 31;
    const int gw = blockIdx.x * 4 + wid, tw = gridDim.x * 4;
    int cnt = g_count; if (cnt > CAP_) cnt = CAP_;
    for (int e = gw; e < cnt; e += tw) {
        int ent = g_list[e], m = ent & 7, pg = ent >> 3;
        int n = pg >> 10, s = pg & 1023;
        const float* latb = latent + ((size_t)n * D_ + (size_t)m * DG_) * HW_ + s;
        for (int d = lane; d < DG_; d += 32) qv_s[wid][d] = latb[(size_t)d * HW_];
        __syncwarp();
        const float* wqm = wq + (size_t)m * DG_ * DG_;
#pragma unroll
        for (int ci = 0; ci < 4; ci++) {
            int c = lane + 32 * ci;
            const float* wr = wqm + (size_t)c * DG_;
            dd a; a.h = a.l = 0.f;
            for (int d = 0; d < DG_; d++) a = dd_fma(a, qv_s[wid][d], wr[d]);
            qh_s[wid][c] = a.h; ql_s[wid][c] = a.l;
        }
        __syncwarp();
        const float* lo = logit_out + ((size_t)pg * M_ + m) * K_;
        float l[8], fm = -3.4e38f;
#pragma unroll
        for (int j = 0; j < 8; j++) { l[j] = lo[lane * 8 + j]; fm = fmaxf(fm, l[j]); }
#pragma unroll
        for (int o = 16; o > 0; o >>= 1) fm = fmaxf(fm, __shfl_xor_sync(0xFFFFFFFFu, fm, o));
        float thresh = fm - REF_WIN;
        double bestv = -1e300; int besti = 1 << 30;
        const float* kph = g_KPH + ((size_t)m * K_) * DG_;
        const float* kpl = g_KPL + ((size_t)m * K_) * DG_;
#pragma unroll
        for (int j = 0; j < 8; j++) {
            unsigned b = __ballot_sync(0xFFFFFFFFu, l[j] >= thresh);
            while (b) {
                int src = __ffs(b) - 1; b &= b - 1;
                int k = src * 8 + j;
                const float* kh = kph + (size_t)k * DG_;
                const float* kl = kpl + (size_t)k * DG_;
                dd a; a.h = a.l = 0.f;
#pragma unroll
                for (int ci = 0; ci < 4; ci++) {
                    int c = lane + 32 * ci;
                    dd kp; kp.h = kh[c]; kp.l = kl[c];
                    dd qp; qp.h = qh_s[wid][c]; qp.l = ql_s[wid][c];
                    a = dd_add(a, dd_mul(kp, qp));
                }
                double v = (double)a.h + (double)a.l;
#pragma unroll
                for (int o = 16; o > 0; o >>= 1) v += __shfl_xor_sync(0xFFFFFFFFu, v, o);
                if (v > bestv || (v == bestv && k < besti)) { bestv = v; besti = k; }
            }
        }
        if (lane == 0) code_out[(size_t)pg * M_ + m] = (float)besti;
    }
}

extern "C" void kernel_launch(void* const* d_in, const int* in_sizes, int n_in,
                              void* d_out, int out_size) {
    const float* latent   = (const float*)d_in[0];
    const float* codebook = (const float*)d_in[1];
    const float* wq       = (const float*)d_in[2];
    const float* wk       = (const float*)d_in[3];
    const float* wv       = (const float*)d_in[4];
    const float* unif     = (const float*)d_in[5];
    float* out   = (float*)d_out;
    float* quant = out;
    float* code  = out + QUANT_ELEMS;
    float* logit = out + QUANT_ELEMS + CODE_ELEMS;

    precompute_kernel<<<dim3(K_ / 8, M_), 256>>>(codebook, wq, wk, wv);
    cudaFuncSetAttribute(main_kernel, cudaFuncAttributeMaxDynamicSharedMemorySize, SMEM_TOTAL);
    main_kernel<<<dim3(NPIX_ / 64, M_), 256, SMEM_TOTAL>>>(latent, unif, quant, code, logit);
    refine_kernel<<<128, 128>>>(latent, wq, logit, code);
}

// round 7
// speedup vs baseline: 1.4360x; 1.0819x over previous
#include <cuda_runtime.h>
#include <cuda_bf16.h>
#include <cstdint>

#define M_    8
#define K_    256
#define DG_   128
#define D_    1024
#define HW_   1024
#define NPIX_ 32768
#define QUANT_ELEMS 33554432
#define CODE_ELEMS  262144
#define GAP_THRESH 1e-3f
#define REF_WIN    2e-3f
#define CAP_       32768

__device__ unsigned short g_Ebh[M_ * K_ * DG_];  // E [m][k][d] bf16 hi
__device__ unsigned short g_Ebl[M_ * K_ * DG_];
__device__ unsigned short g_Vth[M_ * DG_ * K_];  // Vt [m][d][k] bf16 hi
__device__ unsigned short g_Vtl[M_ * DG_ * K_];
__device__ float g_KPH[M_ * K_ * DG_];
__device__ float g_KPL[M_ * K_ * DG_];
__device__ int   g_count;
__device__ int   g_list[CAP_];

__device__ __forceinline__ uint32_t smem_to_u32(const void* p) {
    uint32_t a;
    asm("{ .reg .u64 t; cvta.to.shared.u64 t, %1; cvt.u32.u64 %0, t; }" : "=r"(a) : "l"(p));
    return a;
}
__device__ __forceinline__ void ldsm4(uint32_t* r, uint32_t addr) {
    asm volatile("ldmatrix.sync.aligned.m8n8.x4.shared.b16 {%0,%1,%2,%3}, [%4];"
        : "=r"(r[0]), "=r"(r[1]), "=r"(r[2]), "=r"(r[3]) : "r"(addr));
}
__device__ __forceinline__ void mma_bf16(float* d, const uint32_t* a, const uint32_t* b) {
    asm volatile("mma.sync.aligned.m16n8k16.row.col.f32.bf16.bf16.f32 "
        "{%0,%1,%2,%3}, {%4,%5,%6,%7}, {%8,%9}, {%0,%1,%2,%3};"
        : "+f"(d[0]), "+f"(d[1]), "+f"(d[2]), "+f"(d[3])
        : "r"(a[0]), "r"(a[1]), "r"(a[2]), "r"(a[3]), "r"(b[0]), "r"(b[1]));
}

struct dd { float h, l; };
__device__ __forceinline__ dd two_sum(float a, float b) {
    float s = __fadd_rn(a, b), bb = __fsub_rn(s, a);
    float e = __fadd_rn(__fsub_rn(a, __fsub_rn(s, bb)), __fsub_rn(b, bb));
    dd r; r.h = s; r.l = e; return r;
}
__device__ __forceinline__ dd two_prod(float a, float b) {
    float p = __fmul_rn(a, b), e = __fmaf_rn(a, b, -p);
    dd r; r.h = p; r.l = e; return r;
}
__device__ __forceinline__ dd dd_add(dd x, dd y) {
    dd s = two_sum(x.h, y.h);
    float lo = __fadd_rn(__fadd_rn(x.l, y.l), s.l);
    float hi = __fadd_rn(s.h, lo);
    float l = __fadd_rn(__fsub_rn(s.h, hi), lo);
    dd r; r.h = hi; r.l = l; return r;
}
__device__ __forceinline__ dd dd_fma(dd a, float x, float y) { return dd_add(a, two_prod(x, y)); }
__device__ __forceinline__ dd dd_mul(dd x, dd y) {
    dd p = two_prod(x.h, y.h);
    float t = __fmaf_rn(x.h, y.l, p.l); t = __fmaf_rn(x.l, y.h, t);
    float hi = __fadd_rn(p.h, t), l = __fadd_rn(__fsub_rn(p.h, hi), t);
    dd r; r.h = hi; r.l = l; return r;
}
__device__ __forceinline__ void bf16_split(float v, unsigned short &h, unsigned short &l) {
    __nv_bfloat16 bh = __float2bfloat16(v);
    float hf = __bfloat162float(bh);
    h = __bfloat16_as_ushort(bh);
    l = __bfloat16_as_ushort(__float2bfloat16(v - hf));
}
__device__ __forceinline__ float neglog_acc(float u) {
    float t = __fsub_rn(u, 1.0f);
    float p = fmaf(t, 0.142857143f, -0.166666667f);
    p = fmaf(t, p, 0.2f); p = fmaf(t, p, -0.25f);
    p = fmaf(t, p, 0.333333333f); p = fmaf(t, p, -0.5f); p = fmaf(t, p, 1.0f);
    return (u > 0.75f) ? -(t * p) : -__logf(u);
}

// ---------------- precompute: kproj(dd), Vt/E bf16 splits ----------------
#define P_CB 0
#define P_KP 1024
#define P_WK 2048
#define P_WV (2048 + 4224)
#define P_WQ 2048
#define P_FLOATS (2048 + 4224 + 4224)

__global__ void __launch_bounds__(256)
precompute_kernel(const float* __restrict__ codebook, const float* __restrict__ wq,
                  const float* __restrict__ wk, const float* __restrict__ wv) {
    __shared__ float sm[P_FLOATS];
    float *cbs = sm + P_CB, *kps = sm + P_KP, *wks = sm + P_WK, *wvs = sm + P_WV, *wqs = sm + P_WQ;
    const int m = blockIdx.y, k0 = blockIdx.x * 8, tid = threadIdx.x;
    const int c = tid & 127, khalf = tid >> 7;
    if (m == 0 && blockIdx.x == 0 && tid == 0) g_count = 0;
#pragma unroll
    for (int r = 0; r < 4; r++) {
        int idx = tid + 256 * r;
        cbs[idx] = codebook[((size_t)m * K_ + k0) * DG_ + idx];
    }
    dd sk[4]; float sv[4];
#pragma unroll
    for (int i = 0; i < 4; i++) { sk[i].h = sk[i].l = 0.f; sv[i] = 0.f; }
    const float* wkm = wk + (size_t)m * DG_ * DG_;
    const float* wvm = wv + (size_t)m * DG_ * DG_;
    for (int dc = 0; dc < DG_; dc += 32) {
        __syncthreads();
#pragma unroll
        for (int r = 0; r < 16; r++) {
            int idx = tid + 256 * r, cc = idx >> 5, j = idx & 31;
            wks[cc * 33 + j] = wkm[(size_t)cc * DG_ + dc + j];
            wvs[cc * 33 + j] = wvm[(size_t)cc * DG_ + dc + j];
        }
        __syncthreads();
#pragma unroll 4
        for (int j = 0; j < 32; j++) {
            float wkv = wks[c * 33 + j], wvv = wvs[c * 33 + j];
#pragma unroll
            for (int i = 0; i < 4; i++) {
                float cbv = cbs[(khalf * 4 + i) * DG_ + dc + j];
                sk[i] = dd_fma(sk[i], cbv, wkv);
                sv[i] = fmaf(cbv, wvv, sv[i]);
            }
        }
    }
#pragma unroll
    for (int i = 0; i < 4; i++) {
        int kk = k0 + khalf * 4 + i;
        size_t gb = ((size_t)m * K_ + kk) * DG_ + c;
        g_KPH[gb] = sk[i].h; g_KPL[gb] = sk[i].l;
        unsigned short vh, vl; bf16_split(sv[i], vh, vl);
        size_t vt = ((size_t)m * DG_ + c) * K_ + kk;
        g_Vth[vt] = vh; g_Vtl[vt] = vl;
        kps[(khalf * 4 + i) * DG_ + c] = sk[i].h;
    }
    const int d = c;
    float ea[4] = {0.f, 0.f, 0.f, 0.f};
    const float* wqm = wq + (size_t)m * DG_ * DG_;
    for (int c0 = 0; c0 < DG_; c0 += 32) {
        __syncthreads();
#pragma unroll
        for (int r = 0; r < 16; r++) {
            int idx = tid + 256 * r;
            wqs[idx] = wqm[(size_t)c0 * DG_ + idx];
        }
        __syncthreads();
#pragma unroll 4
        for (int cc = 0; cc < 32; cc++) {
            float wv_ = wqs[cc * DG_ + d];
#pragma unroll
            for (int i = 0; i < 4; i++)
                ea[i] = fmaf(kps[(khalf * 4 + i) * DG_ + c0 + cc], wv_, ea[i]);
        }
    }
#pragma unroll
    for (int i = 0; i < 4; i++) {
        int kk = k0 + khalf * 4 + i;
        unsigned short eh, el; bf16_split(ea[i], eh, el);
        size_t eb = ((size_t)m * K_ + kk) * DG_ + d;
        g_Ebh[eb] = eh; g_Ebl[eb] = el;
    }
}

// ---------------- main mma.sync kernel: 64 pix x fixed m ----------------
#define SM_B1S 0
#define SM_B2S 512
#define SM_I1S 1024
#define SM_SUMS 1536
#define SM_RI  2048
#define SM_STAGE 4096
#define SM_AH (SM_STAGE)
#define SM_AL (SM_STAGE + 5120)
#define SM_EH (SM_STAGE + 10240)
#define SM_EL (SM_STAGE + 30720)
#define SM_VH0 (SM_STAGE)
#define SM_VL0 (SM_STAGE + 10240)
#define SM_VH1 (SM_STAGE + 20480)
#define SM_VL1 (SM_STAGE + 30720)
#define SM_QB  (SM_STAGE)
#define SMEM_TOTAL (4096 + 51200)

#define UPD(b1, b2, i1, v, k) do { \
    if ((v) > (b1)) { b2 = b1; b1 = (v); i1 = (k); } \
    else if ((v) > (b2)) b2 = (v); } while (0)

// register-prefetch macros (loads for chunk c issued ahead of its compute)
#define LOAD_A(c4) do { _Pragma("unroll") \
    for (int j = 0; j < 4; j++) { \
        int dp = (tid >> 6) + 4 * j, pix = tid & 63; \
        pfA[2 * j]     = latb[(size_t)(32 * (c4) + 2 * dp) * HW_ + pix]; \
        pfA[2 * j + 1] = latb[(size_t)(32 * (c4) + 2 * dp + 1) * HW_ + pix]; \
    } } while (0)
#define LOAD_E(c4) do { _Pragma("unroll") \
    for (int j = 0; j < 4; j++) { \
        int q = tid + 256 * j; \
        size_t si = (size_t)(q >> 2) * 16 + (c4) * 4 + (q & 3); \
        pfEh[j] = ebH[si]; pfEl[j] = ebL[si]; \
    } } while (0)
#define STORE_AE() do { _Pragma("unroll") \
    for (int j = 0; j < 4; j++) { \
        int dp = (tid >> 6) + 4 * j, pix = tid & 63; \
        unsigned short h0, l0, h1, l1; \
        bf16_split(pfA[2 * j], h0, l0); bf16_split(pfA[2 * j + 1], h1, l1); \
        *(uint32_t*)(smem + SM_AH + pix * 80 + dp * 4) = ((uint32_t)h1 << 16) | h0; \
        *(uint32_t*)(smem + SM_AL + pix * 80 + dp * 4) = ((uint32_t)l1 << 16) | l0; \
        int q = tid + 256 * j, kR = q >> 2, dc = q & 3; \
        *(uint4*)(smem + SM_EH + kR * 80 + dc * 16) = pfEh[j]; \
        *(uint4*)(smem + SM_EL + kR * 80 + dc * 16) = pfEl[j]; \
    } } while (0)
#define LOAD_V(it) do { _Pragma("unroll") \
    for (int jj = 0; jj < 2; jj++) { \
        int q = tid + 256 * jj, dR = q >> 2, kc = q & 3; \
        size_t si = (size_t)dR * 32 + (it) * 4 + kc; \
        pfV[4 * jj]     = vtH[si];      pfV[4 * jj + 1] = vtL[si]; \
        pfV[4 * jj + 2] = vtH[si + 16]; pfV[4 * jj + 3] = vtL[si + 16]; \
    } } while (0)
#define STORE_V() do { _Pragma("unroll") \
    for (int jj = 0; jj < 2; jj++) { \
        int q = tid + 256 * jj, dR = q >> 2, kc = q & 3; \
        *(uint4*)(smem + SM_VH0 + dR * 80 + kc * 16) = pfV[4 * jj]; \
        *(uint4*)(smem + SM_VL0 + dR * 80 + kc * 16) = pfV[4 * jj + 1]; \
        *(uint4*)(smem + SM_VH1 + dR * 80 + kc * 16) = pfV[4 * jj + 2]; \
        *(uint4*)(smem + SM_VL1 + dR * 80 + kc * 16) = pfV[4 * jj + 3]; \
    } } while (0)

__global__ void __launch_bounds__(256, 1)
main_kernel(const float* __restrict__ latent, const float* __restrict__ unif,
            float* __restrict__ quant_out, float* __restrict__ code_out,
            float* __restrict__ logit_out) {
    extern __shared__ char smem[];
    const uint32_t sb = smem_to_u32(smem);
    const int m = blockIdx.y, p0 = blockIdx.x * 64;
    const int n = p0 >> 10, s0 = p0 & 1023;
    const int tid = threadIdx.x, w = tid >> 5, lane = tid & 31;
    const int wp = w >> 1, wk = w & 1;
    const int gid = lane >> 2, tig = lane & 3;
    const int li = lane & 7, lg = lane >> 3;

    float* b1s = (float*)(smem + SM_B1S);
    float* b2s = (float*)(smem + SM_B2S);
    int*   i1s = (int*)(smem + SM_I1S);
    float* sums = (float*)(smem + SM_SUMS);
    float* rinv = (float*)(smem + SM_RI);
    float* qbuf = (float*)(smem + SM_QB);

    const int a_row = wp * 16 + ((lg & 1) << 3) + li;
    const int a_col = ((lg >> 1) << 3);
    const int b_row = ((lg >> 1) << 3) + li;
    const int b_col = ((lg & 1) << 3);
    const uint32_t aAh = sb + SM_AH + a_row * 80 + a_col * 2;
    const uint32_t aAl = sb + SM_AL + a_row * 80 + a_col * 2;
    const uint32_t aEh = sb + SM_EH + (wk * 128 + b_row) * 80 + b_col * 2;
    const uint32_t aEl = sb + SM_EL + (wk * 128 + b_row) * 80 + b_col * 2;

    const float* latb = latent + ((size_t)n * D_ + (size_t)m * DG_) * HW_ + s0;
    const uint4* ebH = (const uint4*)(g_Ebh + (size_t)m * K_ * DG_);
    const uint4* ebL = (const uint4*)(g_Ebl + (size_t)m * K_ * DG_);
    const uint4* vtH = (const uint4*)(g_Vth + (size_t)m * DG_ * K_);
    const uint4* vtL = (const uint4*)(g_Vtl + (size_t)m * DG_ * K_);

    // ================= GEMM1: logits[64 pix][256 k] =================
    float acc[16][4];
#pragma unroll
    for (int i = 0; i < 16; i++)
#pragma unroll
        for (int j = 0; j < 4; j++) acc[i][j] = 0.f;

    float pfA[8];
    uint4 pfEh[4], pfEl[4];
    LOAD_A(0); LOAD_E(0);

    for (int c4 = 0; c4 < 4; c4++) {
        STORE_AE();
        __syncthreads();
        if (c4 < 3) { LOAD_A(c4 + 1); LOAD_E(c4 + 1); }   // overlap with mma below
#pragma unroll
        for (int s = 0; s < 2; s++) {
            uint32_t ah[4], al[4];
            ldsm4(ah, aAh + s * 32);
            ldsm4(al, aAl + s * 32);
#pragma unroll
            for (int nf2 = 0; nf2 < 8; nf2++) {
                uint32_t bh[4], bl[4];
                ldsm4(bh, aEh + nf2 * 1280 + s * 32);
                ldsm4(bl, aEl + nf2 * 1280 + s * 32);
                mma_bf16(acc[2 * nf2], ah, bh);
                mma_bf16(acc[2 * nf2], ah, bl);
                mma_bf16(acc[2 * nf2], al, bh);
                mma_bf16(acc[2 * nf2 + 1], ah, bh + 2);
                mma_bf16(acc[2 * nf2 + 1], ah, bl + 2);
                mma_bf16(acc[2 * nf2 + 1], al, bh + 2);
            }
        }
        __syncthreads();
    }

    // ================= Epilogue =================
    const int p_r = wp * 16 + gid;
    const size_t pgA = (size_t)(p0 + p_r), pgB = pgA + 8;
    float* lpA = logit_out + (pgA * M_ + m) * K_ + wk * 128 + 2 * tig;
    float* lpB = logit_out + (pgB * M_ + m) * K_ + wk * 128 + 2 * tig;
    const float* upA = unif + (pgA * M_ + m) * K_ + wk * 128 + 2 * tig;
    const float* upB = unif + (pgB * M_ + m) * K_ + wk * 128 + 2 * tig;

    float b1r[2] = {-3.4e38f, -3.4e38f}, b2r[2] = {-3.4e38f, -3.4e38f};
    int i1r[2] = {0, 0};
    float sumr[2] = {0.f, 0.f};
    uint32_t sfh[8][4], sfl[8][4];

#pragma unroll
    for (int nf = 0; nf < 16; nf++) {
        int kk = wk * 128 + nf * 8 + 2 * tig;
        float l00 = acc[nf][0], l01 = acc[nf][1], l10 = acc[nf][2], l11 = acc[nf][3];
        *(float2*)(lpA + nf * 8) = make_float2(l00, l01);
        *(float2*)(lpB + nf * 8) = make_float2(l10, l11);
        float2 u0 = *(const float2*)(upA + nf * 8);
        float2 u1 = *(const float2*)(upB + nf * 8);
        UPD(b1r[0], b2r[0], i1r[0], l00, kk);
        UPD(b1r[0], b2r[0], i1r[0], l01, kk + 1);
        UPD(b1r[1], b2r[1], i1r[1], l10, kk);
        UPD(b1r[1], b2r[1], i1r[1], l11, kk + 1);
        // e = exp(l + g) = exp(l) / (-log u)   (one MUFU log fewer than before)
        float e00 = __fdividef(__expf(l00), neglog_acc(u0.x));
        float e01 = __fdividef(__expf(l01), neglog_acc(u0.y));
        float e10 = __fdividef(__expf(l10), neglog_acc(u1.x));
        float e11 = __fdividef(__expf(l11), neglog_acc(u1.y));
        sumr[0] += e00 + e01;
        sumr[1] += e10 + e11;
        unsigned short h00, lo00, h01, lo01, h10, lo10, h11, lo11;
        bf16_split(e00, h00, lo00); bf16_split(e01, h01, lo01);
        bf16_split(e10, h10, lo10); bf16_split(e11, h11, lo11);
        int s = nf >> 1, off = (nf & 1) * 2;
        sfh[s][off]     = ((uint32_t)h01 << 16) | h00;
        sfh[s][off + 1] = ((uint32_t)h11 << 16) | h10;
        sfl[s][off]     = ((uint32_t)lo01 << 16) | lo00;
        sfl[s][off + 1] = ((uint32_t)lo11 << 16) | lo10;
    }

    uint4 pfV[8];
    LOAD_V(0);    // acc dead now; overlap Vt loads with shuffles/combine below

#pragma unroll
    for (int r = 0; r < 2; r++) {
#pragma unroll
        for (int o = 1; o <= 2; o <<= 1) {
            float ob1 = __shfl_xor_sync(0xFFFFFFFFu, b1r[r], o);
            int   oi1 = __shfl_xor_sync(0xFFFFFFFFu, i1r[r], o);
            float ob2 = __shfl_xor_sync(0xFFFFFFFFu, b2r[r], o);
            if (ob1 > b1r[r] || (ob1 == b1r[r] && oi1 < i1r[r])) {
                b2r[r] = fmaxf(b1r[r], ob2); b1r[r] = ob1; i1r[r] = oi1;
            } else b2r[r] = fmaxf(b2r[r], ob1);
            sumr[r] += __shfl_xor_sync(0xFFFFFFFFu, sumr[r], o);
        }
    }
    if (tig == 0) {
        b1s[wk * 64 + p_r] = b1r[0];  b1s[wk * 64 + p_r + 8] = b1r[1];
        b2s[wk * 64 + p_r] = b2r[0];  b2s[wk * 64 + p_r + 8] = b2r[1];
        i1s[wk * 64 + p_r] = i1r[0];  i1s[wk * 64 + p_r + 8] = i1r[1];
        sums[wk * 64 + p_r] = sumr[0]; sums[wk * 64 + p_r + 8] = sumr[1];
    }
    __syncthreads();

    if (tid < 64) {
        const int p = tid;
        const size_t pg = (size_t)(p0 + p);
        float a1 = b1s[p], a2 = b2s[p];           int ai = i1s[p];
        float c1 = b1s[64 + p], c2 = b2s[64 + p]; int ci = i1s[64 + p];
        float b1, b2; int i1;
        if (a1 >= c1) { b1 = a1; i1 = ai; b2 = fmaxf(a2, fmaxf(c1, c2)); }
        else          { b1 = c1; i1 = ci; b2 = fmaxf(c2, fmaxf(a1, a2)); }
        rinv[p] = 1.0f / (sums[p] + sums[64 + p]);
        code_out[pg * M_ + m] = (float)i1;
        if (b1 - b2 < GAP_THRESH) {
            int idx = atomicAdd(&g_count, 1);
            if (idx < CAP_) g_list[idx] = (int)(pg * M_ + m);
        }
    }

    // ================= GEMM2: quant[64 pix][128 d] = S x Vt^T =================
    float acc2[16][4];
#pragma unroll
    for (int i = 0; i < 16; i++)
#pragma unroll
        for (int j = 0; j < 4; j++) acc2[i][j] = 0.f;

    const uint32_t bvh = sb + (wk ? SM_VH1 : SM_VH0) + b_row * 80 + b_col * 2;
    const uint32_t bvl = sb + (wk ? SM_VL1 : SM_VL0) + b_row * 80 + b_col * 2;

    for (int it = 0; it < 4; it++) {
        STORE_V();
        __syncthreads();
        if (it < 3) LOAD_V(it + 1);   // overlap with mma below
#pragma unroll
        for (int s = 0; s < 2; s++) {
            const int sk = it * 2 + s;
#pragma unroll
            for (int nf2 = 0; nf2 < 8; nf2++) {
                uint32_t bh[4], bl[4];
                ldsm4(bh, bvh + nf2 * 1280 + s * 32);
                ldsm4(bl, bvl + nf2 * 1280 + s * 32);
                mma_bf16(acc2[2 * nf2], sfh[sk], bh);
                mma_bf16(acc2[2 * nf2], sfh[sk], bl);
                mma_bf16(acc2[2 * nf2], sfl[sk], bh);
                mma_bf16(acc2[2 * nf2 + 1], sfh[sk], bh + 2);
                mma_bf16(acc2[2 * nf2 + 1], sfh[sk], bl + 2);
                mma_bf16(acc2[2 * nf2 + 1], sfl[sk], bh + 2);
            }
        }
        __syncthreads();
    }

    // combine k-half partials in smem [64 pix][129]
    if (wk == 0) {
#pragma unroll
        for (int nf = 0; nf < 16; nf++) {
            int d = 8 * nf + 2 * tig;
            qbuf[p_r * 129 + d]       = acc2[nf][0];
            qbuf[p_r * 129 + d + 1]   = acc2[nf][1];
            qbuf[(p_r + 8) * 129 + d]     = acc2[nf][2];
            qbuf[(p_r + 8) * 129 + d + 1] = acc2[nf][3];
        }
    }
    __syncthreads();
    if (wk == 1) {
#pragma unroll
        for (int nf = 0; nf < 16; nf++) {
            int d = 8 * nf + 2 * tig;
            qbuf[p_r * 129 + d]       += acc2[nf][0];
            qbuf[p_r * 129 + d + 1]   += acc2[nf][1];
            qbuf[(p_r + 8) * 129 + d]     += acc2[nf][2];
            qbuf[(p_r + 8) * 129 + d + 1] += acc2[nf][3];
        }
    }
    __syncthreads();

    {
        const int pix = tid & 63, dg2 = tid >> 6;
        const float ri = rinv[pix];
        float* qb = quant_out + ((size_t)n * D_ + (size_t)m * DG_) * HW_ + s0 + pix;
#pragma unroll
        for (int j = 0; j < 32; j++) {
            int d = dg2 * 32 + j;
            qb[(size_t)d * HW_] = qbuf[pix * 129 + d] * ri;
        }
    }
}

// ---------------- refine: dd-exact argmax for near-tie pixels ----------------
__global__ void __launch_bounds__(128)
refine_kernel(const float* __restrict__ latent, const float* __restrict__ wq,
              const float* __restrict__ logit_out, float* __restrict__ code_out) {
    __shared__ float qv_s[4][DG_], qh_s[4][DG_], ql_s[4][DG_];
    const int wid = threadIdx.x >> 5, lane = threadIdx.x & 31;
    const int gw = blockIdx.x * 4 + wid, tw = gridDim.x * 4;
    int cnt = g_count; if (cnt > CAP_) cnt = CAP_;
    for (int e = gw; e < cnt; e += tw) {
        int ent = g_list[e], m = ent & 7, pg = ent >> 3;
        int n = pg >> 10, s = pg & 1023;
        const float* latb = latent + ((size_t)n * D_ + (size_t)m * DG_) * HW_ + s;
        for (int d = lane; d < DG_; d += 32) qv_s[wid][d] = latb[(size_t)d * HW_];
        __syncwarp();
        const float* wqm = wq + (size_t)m * DG_ * DG_;
#pragma unroll
        for (int ci = 0; ci < 4; ci++) {
            int c = lane + 32 * ci;
            const float* wr = wqm + (size_t)c * DG_;
            dd a; a.h = a.l = 0.f;
            for (int d = 0; d < DG_; d++) a = dd_fma(a, qv_s[wid][d], wr[d]);
            qh_s[wid][c] = a.h; ql_s[wid][c] = a.l;
        }
        __syncwarp();
        const float* lo = logit_out + ((size_t)pg * M_ + m) * K_;
        float l[8], fm = -3.4e38f;
#pragma unroll
        for (int j = 0; j < 8; j++) { l[j] = lo[lane * 8 + j]; fm = fmaxf(fm, l[j]); }
#pragma unroll
        for (int o = 16; o > 0; o >>= 1) fm = fmaxf(fm, __shfl_xor_sync(0xFFFFFFFFu, fm, o));
        float thresh = fm - REF_WIN;
        double bestv = -1e300; int besti = 1 << 30;
        const float* kph = g_KPH + ((size_t)m * K_) * DG_;
        const float* kpl = g_KPL + ((size_t)m * K_) * DG_;
#pragma unroll
        for (int j = 0; j < 8; j++) {
            unsigned b = __ballot_sync(0xFFFFFFFFu, l[j] >= thresh);
            while (b) {
                int src = __ffs(b) - 1; b &= b - 1;
                int k = src * 8 + j;
                const float* kh = kph + (size_t)k * DG_;
                const float* kl = kpl + (size_t)k * DG_;
                dd a; a.h = a.l = 0.f;
#pragma unroll
                for (int ci = 0; ci < 4; ci++) {
                    int c = lane + 32 * ci;
                    dd kp; kp.h = kh[c]; kp.l = kl[c];
                    dd qp; qp.h = qh_s[wid][c]; qp.l = ql_s[wid][c];
                    a = dd_add(a, dd_mul(kp, qp));
                }
                double v = (double)a.h + (double)a.l;
#pragma unroll
                for (int o = 16; o > 0; o >>= 1) v += __shfl_xor_sync(0xFFFFFFFFu, v, o);
                if (v > bestv || (v == bestv && k < besti)) { bestv = v; besti = k; }
            }
        }
        if (lane == 0) code_out[(size_t)pg * M_ + m] = (float)besti;
    }
}

extern "C" void kernel_launch(void* const* d_in, const int* in_sizes, int n_in,
                              void* d_out, int out_size) {
    const float* latent   = (const float*)d_in[0];
    const float* codebook = (const float*)d_in[1];
    const float* wq       = (const float*)d_in[2];
    const float* wk       = (const float*)d_in[3];
    const float* wv       = (const float*)d_in[4];
    const float* unif     = (const float*)d_in[5];
    float* out   = (float*)d_out;
    float* quant = out;
    float* code  = out + QUANT_ELEMS;
    float* logit = out + QUANT_ELEMS + CODE_ELEMS;

    precompute_kernel<<<dim3(K_ / 8, M_), 256>>>(codebook, wq, wk, wv);
    cudaFuncSetAttribute(main_kernel, cudaFuncAttributeMaxDynamicSharedMemorySize, SMEM_TOTAL);
    main_kernel<<<dim3(NPIX_ / 64, M_), 256, SMEM_TOTAL>>>(latent, unif, quant, code, logit);
    refine_kernel<<<128, 128>>>(latent, wq, logit, code);
}

// round 8
// speedup vs baseline: 1.7307x; 1.2053x over previous
#include <cuda_runtime.h>
#include <cuda_bf16.h>
#include <cstdint>

#define M_    8
#define K_    256
#define DG_   128
#define D_    1024
#define HW_   1024
#define NPIX_ 32768
#define QUANT_ELEMS 33554432
#define CODE_ELEMS  262144
#define GAP_THRESH 1e-3f
#define REF_WIN    2e-3f
#define CAP_       32768

__device__ unsigned short g_Ebh[M_ * K_ * DG_];  // E [m][k][d] bf16 hi
__device__ unsigned short g_Ebl[M_ * K_ * DG_];
__device__ unsigned short g_Vth[M_ * DG_ * K_];  // Vt [m][d][k] bf16 hi
__device__ unsigned short g_Vtl[M_ * DG_ * K_];
__device__ float g_KPH[M_ * K_ * DG_];
__device__ float g_KPL[M_ * K_ * DG_];
__device__ int   g_count;
__device__ int   g_list[CAP_];

__device__ __forceinline__ uint32_t smem_to_u32(const void* p) {
    uint32_t a;
    asm("{ .reg .u64 t; cvta.to.shared.u64 t, %1; cvt.u32.u64 %0, t; }" : "=r"(a) : "l"(p));
    return a;
}
__device__ __forceinline__ void ldsm4(uint32_t* r, uint32_t addr) {
    asm volatile("ldmatrix.sync.aligned.m8n8.x4.shared.b16 {%0,%1,%2,%3}, [%4];"
        : "=r"(r[0]), "=r"(r[1]), "=r"(r[2]), "=r"(r[3]) : "r"(addr));
}
__device__ __forceinline__ void mma_bf16(float* d, const uint32_t* a, const uint32_t* b) {
    asm volatile("mma.sync.aligned.m16n8k16.row.col.f32.bf16.bf16.f32 "
        "{%0,%1,%2,%3}, {%4,%5,%6,%7}, {%8,%9}, {%0,%1,%2,%3};"
        : "+f"(d[0]), "+f"(d[1]), "+f"(d[2]), "+f"(d[3])
        : "r"(a[0]), "r"(a[1]), "r"(a[2]), "r"(a[3]), "r"(b[0]), "r"(b[1]));
}

struct dd { float h, l; };
__device__ __forceinline__ dd two_sum(float a, float b) {
    float s = __fadd_rn(a, b), bb = __fsub_rn(s, a);
    float e = __fadd_rn(__fsub_rn(a, __fsub_rn(s, bb)), __fsub_rn(b, bb));
    dd r; r.h = s; r.l = e; return r;
}
__device__ __forceinline__ dd two_prod(float a, float b) {
    float p = __fmul_rn(a, b), e = __fmaf_rn(a, b, -p);
    dd r; r.h = p; r.l = e; return r;
}
__device__ __forceinline__ dd dd_add(dd x, dd y) {
    dd s = two_sum(x.h, y.h);
    float lo = __fadd_rn(__fadd_rn(x.l, y.l), s.l);
    float hi = __fadd_rn(s.h, lo);
    float l = __fadd_rn(__fsub_rn(s.h, hi), lo);
    dd r; r.h = hi; r.l = l; return r;
}
__device__ __forceinline__ dd dd_fma(dd a, float x, float y) { return dd_add(a, two_prod(x, y)); }
__device__ __forceinline__ dd dd_mul(dd x, dd y) {
    dd p = two_prod(x.h, y.h);
    float t = __fmaf_rn(x.h, y.l, p.l); t = __fmaf_rn(x.l, y.h, t);
    float hi = __fadd_rn(p.h, t), l = __fadd_rn(__fsub_rn(p.h, hi), t);
    dd r; r.h = hi; r.l = l; return r;
}
__device__ __forceinline__ void bf16_split(float v, unsigned short &h, unsigned short &l) {
    __nv_bfloat16 bh = __float2bfloat16(v);
    float hf = __bfloat162float(bh);
    h = __bfloat16_as_ushort(bh);
    l = __bfloat16_as_ushort(__float2bfloat16(v - hf));
}
__device__ __forceinline__ float neglog_acc(float u) {
    float t = __fsub_rn(u, 1.0f);
    float p = fmaf(t, 0.142857143f, -0.166666667f);
    p = fmaf(t, p, 0.2f); p = fmaf(t, p, -0.25f);
    p = fmaf(t, p, 0.333333333f); p = fmaf(t, p, -0.5f); p = fmaf(t, p, 1.0f);
    return (u > 0.75f) ? -(t * p) : -__logf(u);
}

// ---------------- precompute: kproj(dd), Vt/E bf16 splits ----------------
#define P_CB 0
#define P_KP 1024
#define P_WK 2048
#define P_WV (2048 + 4224)
#define P_WQ 2048
#define P_FLOATS (2048 + 4224 + 4224)

__global__ void __launch_bounds__(256)
precompute_kernel(const float* __restrict__ codebook, const float* __restrict__ wq,
                  const float* __restrict__ wk, const float* __restrict__ wv) {
    __shared__ float sm[P_FLOATS];
    float *cbs = sm + P_CB, *kps = sm + P_KP, *wks = sm + P_WK, *wvs = sm + P_WV, *wqs = sm + P_WQ;
    const int m = blockIdx.y, k0 = blockIdx.x * 8, tid = threadIdx.x;
    const int c = tid & 127, khalf = tid >> 7;
    if (m == 0 && blockIdx.x == 0 && tid == 0) g_count = 0;
#pragma unroll
    for (int r = 0; r < 4; r++) {
        int idx = tid + 256 * r;
        cbs[idx] = codebook[((size_t)m * K_ + k0) * DG_ + idx];
    }
    dd sk[4]; float sv[4];
#pragma unroll
    for (int i = 0; i < 4; i++) { sk[i].h = sk[i].l = 0.f; sv[i] = 0.f; }
    const float* wkm = wk + (size_t)m * DG_ * DG_;
    const float* wvm = wv + (size_t)m * DG_ * DG_;
    for (int dc = 0; dc < DG_; dc += 32) {
        __syncthreads();
#pragma unroll
        for (int r = 0; r < 16; r++) {
            int idx = tid + 256 * r, cc = idx >> 5, j = idx & 31;
            wks[cc * 33 + j] = wkm[(size_t)cc * DG_ + dc + j];
            wvs[cc * 33 + j] = wvm[(size_t)cc * DG_ + dc + j];
        }
        __syncthreads();
#pragma unroll 4
        for (int j = 0; j < 32; j++) {
            float wkv = wks[c * 33 + j], wvv = wvs[c * 33 + j];
#pragma unroll
            for (int i = 0; i < 4; i++) {
                float cbv = cbs[(khalf * 4 + i) * DG_ + dc + j];
                sk[i] = dd_fma(sk[i], cbv, wkv);
                sv[i] = fmaf(cbv, wvv, sv[i]);
            }
        }
    }
#pragma unroll
    for (int i = 0; i < 4; i++) {
        int kk = k0 + khalf * 4 + i;
        size_t gb = ((size_t)m * K_ + kk) * DG_ + c;
        g_KPH[gb] = sk[i].h; g_KPL[gb] = sk[i].l;
        unsigned short vh, vl; bf16_split(sv[i], vh, vl);
        size_t vt = ((size_t)m * DG_ + c) * K_ + kk;
        g_Vth[vt] = vh; g_Vtl[vt] = vl;
        kps[(khalf * 4 + i) * DG_ + c] = sk[i].h;
    }
    const int d = c;
    float ea[4] = {0.f, 0.f, 0.f, 0.f};
    const float* wqm = wq + (size_t)m * DG_ * DG_;
    for (int c0 = 0; c0 < DG_; c0 += 32) {
        __syncthreads();
#pragma unroll
        for (int r = 0; r < 16; r++) {
            int idx = tid + 256 * r;
            wqs[idx] = wqm[(size_t)c0 * DG_ + idx];
        }
        __syncthreads();
#pragma unroll 4
        for (int cc = 0; cc < 32; cc++) {
            float wv_ = wqs[cc * DG_ + d];
#pragma unroll
            for (int i = 0; i < 4; i++)
                ea[i] = fmaf(kps[(khalf * 4 + i) * DG_ + c0 + cc], wv_, ea[i]);
        }
    }
#pragma unroll
    for (int i = 0; i < 4; i++) {
        int kk = k0 + khalf * 4 + i;
        unsigned short eh, el; bf16_split(ea[i], eh, el);
        size_t eb = ((size_t)m * K_ + kk) * DG_ + d;
        g_Ebh[eb] = eh; g_Ebl[eb] = el;
    }
}

// ---------------- main mma.sync kernel: 64 pix x fixed m, 2 CTAs/SM ----------------
// smem byte offsets
#define SM_B1S  0
#define SM_B2S  512
#define SM_I1S  1024
#define SM_SUMS 1536
#define SM_RI   2048
#define SM_SSH  4096                       // S hi: [64 pix][256 k] bf16, 528B rows
#define SM_SSL  (4096 + 33792)             // S lo
#define SM_STG  (4096 + 67584)             // shared stage region (71680)
#define SM_AH   (SM_STG)                   // A chunk hi: [64][16d] 48B rows = 3072
#define SM_AL   (SM_STG + 3072)
#define SM_EH   (SM_STG + 6144)            // E chunk hi: [256][16d] 48B rows = 12288
#define SM_EL   (SM_STG + 6144 + 12288)
#define SM_VH   (SM_STG)                   // V chunk hi: [128][32k] 80B rows = 10240
#define SM_VL   (SM_STG + 10240)
#define SM_QB   (SM_STG)                   // qbuf [64][132] f32 = 33792
#define SMEM_TOTAL (4096 + 67584 + 33792)  // 105472

#define UPD(b1, b2, i1, v, k) do { \
    if ((v) > (b1)) { b2 = b1; b1 = (v); i1 = (k); } \
    else if ((v) > (b2)) b2 = (v); } while (0)

#define LOAD_A(c8) do { _Pragma("unroll") \
    for (int j = 0; j < 2; j++) { \
        int dp = (tid >> 6) + 4 * j, pix = tid & 63; \
        pfA[2 * j]     = latb[(size_t)(16 * (c8) + 2 * dp) * HW_ + pix]; \
        pfA[2 * j + 1] = latb[(size_t)(16 * (c8) + 2 * dp + 1) * HW_ + pix]; \
    } } while (0)
#define LOAD_E(c8) do { _Pragma("unroll") \
    for (int j = 0; j < 2; j++) { \
        size_t si = (size_t)tid * 16 + (c8) * 2 + j; \
        pfEh[j] = ebH[si]; pfEl[j] = ebL[si]; \
    } } while (0)
#define STORE_AE() do { _Pragma("unroll") \
    for (int j = 0; j < 2; j++) { \
        int dp = (tid >> 6) + 4 * j, pix = tid & 63; \
        unsigned short h0, l0, h1, l1; \
        bf16_split(pfA[2 * j], h0, l0); bf16_split(pfA[2 * j + 1], h1, l1); \
        *(uint32_t*)(smem + SM_AH + pix * 48 + dp * 4) = ((uint32_t)h1 << 16) | h0; \
        *(uint32_t*)(smem + SM_AL + pix * 48 + dp * 4) = ((uint32_t)l1 << 16) | l0; \
        *(uint4*)(smem + SM_EH + tid * 48 + j * 16) = pfEh[j]; \
        *(uint4*)(smem + SM_EL + tid * 48 + j * 16) = pfEl[j]; \
    } } while (0)
#define LOAD_V(it) do { _Pragma("unroll") \
    for (int jj = 0; jj < 2; jj++) { \
        int q = tid + 256 * jj, dR = q >> 2, kc = q & 3; \
        size_t si = (size_t)dR * 32 + (it) * 4 + kc; \
        pfV[2 * jj]     = vtH[si]; \
        pfV[2 * jj + 1] = vtL[si]; \
    } } while (0)
#define STORE_V() do { _Pragma("unroll") \
    for (int jj = 0; jj < 2; jj++) { \
        int q = tid + 256 * jj, dR = q >> 2, kc = q & 3; \
        *(uint4*)(smem + SM_VH + dR * 80 + kc * 16) = pfV[2 * jj]; \
        *(uint4*)(smem + SM_VL + dR * 80 + kc * 16) = pfV[2 * jj + 1]; \
    } } while (0)

__global__ void __launch_bounds__(256, 2)
main_kernel(const float* __restrict__ latent, const float* __restrict__ unif,
            float* __restrict__ quant_out, float* __restrict__ code_out,
            float* __restrict__ logit_out) {
    extern __shared__ char smem[];
    const uint32_t sb = smem_to_u32(smem);
    const int m = blockIdx.y, p0 = blockIdx.x * 64;
    const int n = p0 >> 10, s0 = p0 & 1023;
    const int tid = threadIdx.x, w = tid >> 5, lane = tid & 31;
    const int wp = w >> 1, wk = w & 1;      // GEMM1: pix-group x k-half; GEMM2: wk = d-half
    const int gid = lane >> 2, tig = lane & 3;
    const int li = lane & 7, lg = lane >> 3;

    float* b1s = (float*)(smem + SM_B1S);
    float* b2s = (float*)(smem + SM_B2S);
    int*   i1s = (int*)(smem + SM_I1S);
    float* sums = (float*)(smem + SM_SUMS);
    float* rinv = (float*)(smem + SM_RI);
    float* qbuf = (float*)(smem + SM_QB);

    const int a_row = wp * 16 + ((lg & 1) << 3) + li;
    const int a_col = ((lg >> 1) << 3);
    const int b_row = ((lg >> 1) << 3) + li;
    const int b_col = ((lg & 1) << 3);
    const uint32_t aAh = sb + SM_AH + a_row * 48 + a_col * 2;
    const uint32_t aAl = sb + SM_AL + a_row * 48 + a_col * 2;
    const uint32_t aEh = sb + SM_EH + (wk * 128 + b_row) * 48 + b_col * 2;
    const uint32_t aEl = sb + SM_EL + (wk * 128 + b_row) * 48 + b_col * 2;

    const float* latb = latent + ((size_t)n * D_ + (size_t)m * DG_) * HW_ + s0;
    const uint4* ebH = (const uint4*)(g_Ebh + (size_t)m * K_ * DG_);
    const uint4* ebL = (const uint4*)(g_Ebl + (size_t)m * K_ * DG_);
    const uint4* vtH = (const uint4*)(g_Vth + (size_t)m * DG_ * K_);
    const uint4* vtL = (const uint4*)(g_Vtl + (size_t)m * DG_ * K_);

    // ================= GEMM1: logits[64 pix][256 k], d-chunks of 16 =================
    float acc[16][4];
#pragma unroll
    for (int i = 0; i < 16; i++)
#pragma unroll
        for (int j = 0; j < 4; j++) acc[i][j] = 0.f;

    float pfA[4];
    uint4 pfEh[2], pfEl[2];
    LOAD_A(0); LOAD_E(0);

    for (int c8 = 0; c8 < 8; c8++) {
        STORE_AE();
        __syncthreads();
        if (c8 < 7) { LOAD_A(c8 + 1); LOAD_E(c8 + 1); }
        uint32_t ah[4], al[4];
        ldsm4(ah, aAh);
        ldsm4(al, aAl);
#pragma unroll
        for (int nf2 = 0; nf2 < 8; nf2++) {
            uint32_t bh[4], bl[4];
            ldsm4(bh, aEh + nf2 * 768);
            ldsm4(bl, aEl + nf2 * 768);
            mma_bf16(acc[2 * nf2], ah, bh);
            mma_bf16(acc[2 * nf2], ah, bl);
            mma_bf16(acc[2 * nf2], al, bh);
            mma_bf16(acc[2 * nf2 + 1], ah, bh + 2);
            mma_bf16(acc[2 * nf2 + 1], ah, bl + 2);
            mma_bf16(acc[2 * nf2 + 1], al, bh + 2);
        }
        __syncthreads();
    }

    // ================= Epilogue: logits out, gumbel-softmax, S -> smem =================
    const int p_r = wp * 16 + gid;
    const size_t pgA = (size_t)(p0 + p_r), pgB = pgA + 8;
    float* lpA = logit_out + (pgA * M_ + m) * K_ + wk * 128 + 2 * tig;
    float* lpB = logit_out + (pgB * M_ + m) * K_ + wk * 128 + 2 * tig;
    const float* upA = unif + (pgA * M_ + m) * K_ + wk * 128 + 2 * tig;
    const float* upB = unif + (pgB * M_ + m) * K_ + wk * 128 + 2 * tig;

    float b1r[2] = {-3.4e38f, -3.4e38f}, b2r[2] = {-3.4e38f, -3.4e38f};
    int i1r[2] = {0, 0};
    float sumr[2] = {0.f, 0.f};

#pragma unroll
    for (int nf = 0; nf < 16; nf++) {
        int kk = wk * 128 + nf * 8 + 2 * tig;
        float l00 = acc[nf][0], l01 = acc[nf][1], l10 = acc[nf][2], l11 = acc[nf][3];
        *(float2*)(lpA + nf * 8) = make_float2(l00, l01);
        *(float2*)(lpB + nf * 8) = make_float2(l10, l11);
        float2 u0 = *(const float2*)(upA + nf * 8);
        float2 u1 = *(const float2*)(upB + nf * 8);
        UPD(b1r[0], b2r[0], i1r[0], l00, kk);
        UPD(b1r[0], b2r[0], i1r[0], l01, kk + 1);
        UPD(b1r[1], b2r[1], i1r[1], l10, kk);
        UPD(b1r[1], b2r[1], i1r[1], l11, kk + 1);
        float e00 = __fdividef(__expf(l00), neglog_acc(u0.x));
        float e01 = __fdividef(__expf(l01), neglog_acc(u0.y));
        float e10 = __fdividef(__expf(l10), neglog_acc(u1.x));
        float e11 = __fdividef(__expf(l11), neglog_acc(u1.y));
        sumr[0] += e00 + e01;
        sumr[1] += e10 + e11;
        unsigned short h00, lo00, h01, lo01, h10, lo10, h11, lo11;
        bf16_split(e00, h00, lo00); bf16_split(e01, h01, lo01);
        bf16_split(e10, h10, lo10); bf16_split(e11, h11, lo11);
        // S[pix][k] bf16, 528B rows; bank-conflict-free (4*gid + tig pattern)
        *(uint32_t*)(smem + SM_SSH + p_r * 528 + kk * 2)       = ((uint32_t)h01 << 16) | h00;
        *(uint32_t*)(smem + SM_SSH + (p_r + 8) * 528 + kk * 2) = ((uint32_t)h11 << 16) | h10;
        *(uint32_t*)(smem + SM_SSL + p_r * 528 + kk * 2)       = ((uint32_t)lo01 << 16) | lo00;
        *(uint32_t*)(smem + SM_SSL + (p_r + 8) * 528 + kk * 2) = ((uint32_t)lo11 << 16) | lo10;
    }

    uint4 pfV[4];
    LOAD_V(0);

#pragma unroll
    for (int r = 0; r < 2; r++) {
#pragma unroll
        for (int o = 1; o <= 2; o <<= 1) {
            float ob1 = __shfl_xor_sync(0xFFFFFFFFu, b1r[r], o);
            int   oi1 = __shfl_xor_sync(0xFFFFFFFFu, i1r[r], o);
            float ob2 = __shfl_xor_sync(0xFFFFFFFFu, b2r[r], o);
            if (ob1 > b1r[r] || (ob1 == b1r[r] && oi1 < i1r[r])) {
                b2r[r] = fmaxf(b1r[r], ob2); b1r[r] = ob1; i1r[r] = oi1;
            } else b2r[r] = fmaxf(b2r[r], ob1);
            sumr[r] += __shfl_xor_sync(0xFFFFFFFFu, sumr[r], o);
        }
    }
    if (tig == 0) {
        b1s[wk * 64 + p_r] = b1r[0];  b1s[wk * 64 + p_r + 8] = b1r[1];
        b2s[wk * 64 + p_r] = b2r[0];  b2s[wk * 64 + p_r + 8] = b2r[1];
        i1s[wk * 64 + p_r] = i1r[0];  i1s[wk * 64 + p_r + 8] = i1r[1];
        sums[wk * 64 + p_r] = sumr[0]; sums[wk * 64 + p_r + 8] = sumr[1];
    }
    __syncthreads();

    if (tid < 64) {
        const int p = tid;
        const size_t pg = (size_t)(p0 + p);
        float a1 = b1s[p], a2 = b2s[p];           int ai = i1s[p];
        float c1 = b1s[64 + p], c2 = b2s[64 + p]; int ci = i1s[64 + p];
        float b1, b2; int i1;
        if (a1 >= c1) { b1 = a1; i1 = ai; b2 = fmaxf(a2, fmaxf(c1, c2)); }
        else          { b1 = c1; i1 = ci; b2 = fmaxf(c2, fmaxf(a1, a2)); }
        rinv[p] = 1.0f / (sums[p] + sums[64 + p]);
        code_out[pg * M_ + m] = (float)i1;
        if (b1 - b2 < GAP_THRESH) {
            int idx = atomicAdd(&g_count, 1);
            if (idx < CAP_) g_list[idx] = (int)(pg * M_ + m);
        }
    }

    // ================= GEMM2: quant[64 pix][128 d] = S x Vt^T =================
    // warps: wp = pix-group(16), wk = d-half(64); full K=256 from S smem.
    float acc2[8][4];
#pragma unroll
    for (int i = 0; i < 8; i++)
#pragma unroll
        for (int j = 0; j < 4; j++) acc2[i][j] = 0.f;

    const uint32_t aSh = sb + SM_SSH + a_row * 528 + a_col * 2;
    const uint32_t aSl = sb + SM_SSL + a_row * 528 + a_col * 2;
    const uint32_t bvh = sb + SM_VH + (wk * 64 + b_row) * 80 + b_col * 2;
    const uint32_t bvl = sb + SM_VL + (wk * 64 + b_row) * 80 + b_col * 2;

    for (int it = 0; it < 8; it++) {          // k-chunks of 32
        STORE_V();
        __syncthreads();
        if (it < 7) LOAD_V(it + 1);
#pragma unroll
        for (int s = 0; s < 2; s++) {
            const int k0 = it * 32 + s * 16;
            uint32_t sh[4], sl[4];
            ldsm4(sh, aSh + k0 * 2);
            ldsm4(sl, aSl + k0 * 2);
#pragma unroll
            for (int nf2 = 0; nf2 < 4; nf2++) {
                uint32_t bh[4], bl[4];
                ldsm4(bh, bvh + nf2 * 1280 + s * 32);
                ldsm4(bl, bvl + nf2 * 1280 + s * 32);
                mma_bf16(acc2[2 * nf2], sh, bh);
                mma_bf16(acc2[2 * nf2], sh, bl);
                mma_bf16(acc2[2 * nf2], sl, bh);
                mma_bf16(acc2[2 * nf2 + 1], sh, bh + 2);
                mma_bf16(acc2[2 * nf2 + 1], sh, bl + 2);
                mma_bf16(acc2[2 * nf2 + 1], sl, bh + 2);
            }
        }
        __syncthreads();
    }

    // write warp-complete output to qbuf (no combine), then coalesced stores
#pragma unroll
    for (int nf = 0; nf < 8; nf++) {
        int d = wk * 64 + 8 * nf + 2 * tig;
        qbuf[p_r * 132 + d]       = acc2[nf][0];
        qbuf[p_r * 132 + d + 1]   = acc2[nf][1];
        qbuf[(p_r + 8) * 132 + d]     = acc2[nf][2];
        qbuf[(p_r + 8) * 132 + d + 1] = acc2[nf][3];
    }
    __syncthreads();
    {
        const int pix = tid & 63, dg2 = tid >> 6;
        const float ri = rinv[pix];
        float* qb = quant_out + ((size_t)n * D_ + (size_t)m * DG_) * HW_ + s0 + pix;
#pragma unroll
        for (int j = 0; j < 32; j++) {
            int d = dg2 * 32 + j;
            qb[(size_t)d * HW_] = qbuf[pix * 132 + d] * ri;
        }
    }
}

// ---------------- refine: dd-exact argmax for near-tie pixels ----------------
__global__ void __launch_bounds__(128)
refine_kernel(const float* __restrict__ latent, const float* __restrict__ wq,
              const float* __restrict__ logit_out, float* __restrict__ code_out) {
    __shared__ float qv_s[4][DG_], qh_s[4][DG_], ql_s[4][DG_];
    const int wid = threadIdx.x >> 5, lane = threadIdx.x & 31;
    const int gw = blockIdx.x * 4 + wid, tw = gridDim.x * 4;
    int cnt = g_count; if (cnt > CAP_) cnt = CAP_;
    for (int e = gw; e < cnt; e += tw) {
        int ent = g_list[e], m = ent & 7, pg = ent >> 3;
        int n = pg >> 10, s = pg & 1023;
        const float* latb = latent + ((size_t)n * D_ + (size_t)m * DG_) * HW_ + s;
        for (int d = lane; d < DG_; d += 32) qv_s[wid][d] = latb[(size_t)d * HW_];
        __syncwarp();
        const float* wqm = wq + (size_t)m * DG_ * DG_;
#pragma unroll
        for (int ci = 0; ci < 4; ci++) {
            int c = lane + 32 * ci;
            const float* wr = wqm + (size_t)c * DG_;
            dd a; a.h = a.l = 0.f;
            for (int d = 0; d < DG_; d++) a = dd_fma(a, qv_s[wid][d], wr[d]);
            qh_s[wid][c] = a.h; ql_s[wid][c] = a.l;
        }
        __syncwarp();
        const float* lo = logit_out + ((size_t)pg * M_ + m) * K_;
        float l[8], fm = -3.4e38f;
#pragma unroll
        for (int j = 0; j < 8; j++) { l[j] = lo[lane * 8 + j]; fm = fmaxf(fm, l[j]); }
#pragma unroll
        for (int o = 16; o > 0; o >>= 1) fm = fmaxf(fm, __shfl_xor_sync(0xFFFFFFFFu, fm, o));
        float thresh = fm - REF_WIN;
        double bestv = -1e300; int besti = 1 << 30;
        const float* kph = g_KPH + ((size_t)m * K_) * DG_;
        const float* kpl = g_KPL + ((size_t)m * K_) * DG_;
#pragma unroll
        for (int j = 0; j < 8; j++) {
            unsigned b = __ballot_sync(0xFFFFFFFFu, l[j] >= thresh);
            while (b) {
                int src = __ffs(b) - 1; b &= b - 1;
                int k = src * 8 + j;
                const float* kh = kph + (size_t)k * DG_;
                const float* kl = kpl + (size_t)k * DG_;
                dd a; a.h = a.l = 0.f;
#pragma unroll
                for (int ci = 0; ci < 4; ci++) {
                    int c = lane + 32 * ci;
                    dd kp; kp.h = kh[c]; kp.l = kl[c];
                    dd qp; qp.h = qh_s[wid][c]; qp.l = ql_s[wid][c];
                    a = dd_add(a, dd_mul(kp, qp));
                }
                double v = (double)a.h + (double)a.l;
#pragma unroll
                for (int o = 16; o > 0; o >>= 1) v += __shfl_xor_sync(0xFFFFFFFFu, v, o);
                if (v > bestv || (v == bestv && k < besti)) { bestv = v; besti = k; }
            }
        }
        if (lane == 0) code_out[(size_t)pg * M_ + m] = (float)besti;
    }
}

extern "C" void kernel_launch(void* const* d_in, const int* in_sizes, int n_in,
                              void* d_out, int out_size) {
    const float* latent   = (const float*)d_in[0];
    const float* codebook = (const float*)d_in[1];
    const float* wq       = (const float*)d_in[2];
    const float* wk       = (const float*)d_in[3];
    const float* wv       = (const float*)d_in[4];
    const float* unif     = (const float*)d_in[5];
    float* out   = (float*)d_out;
    float* quant = out;
    float* code  = out + QUANT_ELEMS;
    float* logit = out + QUANT_ELEMS + CODE_ELEMS;

    precompute_kernel<<<dim3(K_ / 8, M_), 256>>>(codebook, wq, wk, wv);
    cudaFuncSetAttribute(main_kernel, cudaFuncAttributeMaxDynamicSharedMemorySize, SMEM_TOTAL);
    main_kernel<<<dim3(NPIX_ / 64, M_), 256, SMEM_TOTAL>>>(latent, unif, quant, code, logit);
    refine_kernel<<<128, 128>>>(latent, wq, logit, code);
}

// round 9
// speedup vs baseline: 1.9246x; 1.1120x over previous
#include <cuda_runtime.h>
#include <cuda_fp16.h>
#include <cstdint>

#define M_    8
#define K_    256
#define DG_   128
#define D_    1024
#define HW_   1024
#define NPIX_ 32768
#define QUANT_ELEMS 33554432
#define CODE_ELEMS  262144
#define GAP_THRESH 2e-3f
#define REF_WIN    3e-3f
#define CAP_       32768

__device__ unsigned short g_Eh[M_ * K_ * DG_];   // E [m][k][d] fp16
__device__ unsigned short g_Vh[M_ * DG_ * K_];   // Vt [m][d][k] fp16
__device__ float g_KPH[M_ * K_ * DG_];
__device__ float g_KPL[M_ * K_ * DG_];
__device__ int   g_count;
__device__ int   g_list[CAP_];

__device__ __forceinline__ uint32_t smem_to_u32(const void* p) {
    uint32_t a;
    asm("{ .reg .u64 t; cvta.to.shared.u64 t, %1; cvt.u32.u64 %0, t; }" : "=r"(a) : "l"(p));
    return a;
}
__device__ __forceinline__ void ldsm4(uint32_t* r, uint32_t addr) {
    asm volatile("ldmatrix.sync.aligned.m8n8.x4.shared.b16 {%0,%1,%2,%3}, [%4];"
        : "=r"(r[0]), "=r"(r[1]), "=r"(r[2]), "=r"(r[3]) : "r"(addr));
}
__device__ __forceinline__ void mma_f16(float* d, const uint32_t* a, const uint32_t* b) {
    asm volatile("mma.sync.aligned.m16n8k16.row.col.f32.f16.f16.f32 "
        "{%0,%1,%2,%3}, {%4,%5,%6,%7}, {%8,%9}, {%0,%1,%2,%3};"
        : "+f"(d[0]), "+f"(d[1]), "+f"(d[2]), "+f"(d[3])
        : "r"(a[0]), "r"(a[1]), "r"(a[2]), "r"(a[3]), "r"(b[0]), "r"(b[1]));
}

struct dd { float h, l; };
__device__ __forceinline__ dd two_sum(float a, float b) {
    float s = __fadd_rn(a, b), bb = __fsub_rn(s, a);
    float e = __fadd_rn(__fsub_rn(a, __fsub_rn(s, bb)), __fsub_rn(b, bb));
    dd r; r.h = s; r.l = e; return r;
}
__device__ __forceinline__ dd two_prod(float a, float b) {
    float p = __fmul_rn(a, b), e = __fmaf_rn(a, b, -p);
    dd r; r.h = p; r.l = e; return r;
}
__device__ __forceinline__ dd dd_add(dd x, dd y) {
    dd s = two_sum(x.h, y.h);
    float lo = __fadd_rn(__fadd_rn(x.l, y.l), s.l);
    float hi = __fadd_rn(s.h, lo);
    float l = __fadd_rn(__fsub_rn(s.h, hi), lo);
    dd r; r.h = hi; r.l = l; return r;
}
__device__ __forceinline__ dd dd_fma(dd a, float x, float y) { return dd_add(a, two_prod(x, y)); }
__device__ __forceinline__ dd dd_mul(dd x, dd y) {
    dd p = two_prod(x.h, y.h);
    float t = __fmaf_rn(x.h, y.l, p.l); t = __fmaf_rn(x.l, y.h, t);
    float hi = __fadd_rn(p.h, t), l = __fadd_rn(__fsub_rn(p.h, hi), t);
    dd r; r.h = hi; r.l = l; return r;
}
__device__ __forceinline__ void fp16_split(float v, unsigned short &h, unsigned short &l) {
    __half hh = __float2half_rn(v);
    float hf = __half2float(hh);
    h = __half_as_ushort(hh);
    l = __half_as_ushort(__float2half_rn(v - hf));
}
__device__ __forceinline__ float neglog_acc(float u) {
    float t = __fsub_rn(u, 1.0f);
    float p = fmaf(t, 0.142857143f, -0.166666667f);
    p = fmaf(t, p, 0.2f); p = fmaf(t, p, -0.25f);
    p = fmaf(t, p, 0.333333333f); p = fmaf(t, p, -0.5f); p = fmaf(t, p, 1.0f);
    return (u > 0.75f) ? -(t * p) : -__logf(u);
}

// ---------------- precompute: kproj(dd), Vt/E fp16 ----------------
#define P_CB 0
#define P_KP 1024
#define P_WK 2048
#define P_WV (2048 + 4224)
#define P_WQ 2048
#define P_FLOATS (2048 + 4224 + 4224)

__global__ void __launch_bounds__(256)
precompute_kernel(const float* __restrict__ codebook, const float* __restrict__ wq,
                  const float* __restrict__ wk, const float* __restrict__ wv) {
    __shared__ float sm[P_FLOATS];
    float *cbs = sm + P_CB, *kps = sm + P_KP, *wks = sm + P_WK, *wvs = sm + P_WV, *wqs = sm + P_WQ;
    const int m = blockIdx.y, k0 = blockIdx.x * 8, tid = threadIdx.x;
    const int c = tid & 127, khalf = tid >> 7;
    if (m == 0 && blockIdx.x == 0 && tid == 0) g_count = 0;
#pragma unroll
    for (int r = 0; r < 4; r++) {
        int idx = tid + 256 * r;
        cbs[idx] = codebook[((size_t)m * K_ + k0) * DG_ + idx];
    }
    dd sk[4]; float sv[4];
#pragma unroll
    for (int i = 0; i < 4; i++) { sk[i].h = sk[i].l = 0.f; sv[i] = 0.f; }
    const float* wkm = wk + (size_t)m * DG_ * DG_;
    const float* wvm = wv + (size_t)m * DG_ * DG_;
    for (int dc = 0; dc < DG_; dc += 32) {
        __syncthreads();
#pragma unroll
        for (int r = 0; r < 16; r++) {
            int idx = tid + 256 * r, cc = idx >> 5, j = idx & 31;
            wks[cc * 33 + j] = wkm[(size_t)cc * DG_ + dc + j];
            wvs[cc * 33 + j] = wvm[(size_t)cc * DG_ + dc + j];
        }
        __syncthreads();
#pragma unroll 4
        for (int j = 0; j < 32; j++) {
            float wkv = wks[c * 33 + j], wvv = wvs[c * 33 + j];
#pragma unroll
            for (int i = 0; i < 4; i++) {
                float cbv = cbs[(khalf * 4 + i) * DG_ + dc + j];
                sk[i] = dd_fma(sk[i], cbv, wkv);
                sv[i] = fmaf(cbv, wvv, sv[i]);
            }
        }
    }
#pragma unroll
    for (int i = 0; i < 4; i++) {
        int kk = k0 + khalf * 4 + i;
        size_t gb = ((size_t)m * K_ + kk) * DG_ + c;
        g_KPH[gb] = sk[i].h; g_KPL[gb] = sk[i].l;
        g_Vh[((size_t)m * DG_ + c) * K_ + kk] = __half_as_ushort(__float2half_rn(sv[i]));
        kps[(khalf * 4 + i) * DG_ + c] = sk[i].h;
    }
    const int d = c;
    float ea[4] = {0.f, 0.f, 0.f, 0.f};
    const float* wqm = wq + (size_t)m * DG_ * DG_;
    for (int c0 = 0; c0 < DG_; c0 += 32) {
        __syncthreads();
#pragma unroll
        for (int r = 0; r < 16; r++) {
            int idx = tid + 256 * r;
            wqs[idx] = wqm[(size_t)c0 * DG_ + idx];
        }
        __syncthreads();
#pragma unroll 4
        for (int cc = 0; cc < 32; cc++) {
            float wv_ = wqs[cc * DG_ + d];
#pragma unroll
            for (int i = 0; i < 4; i++)
                ea[i] = fmaf(kps[(khalf * 4 + i) * DG_ + c0 + cc], wv_, ea[i]);
        }
    }
#pragma unroll
    for (int i = 0; i < 4; i++)
        g_Eh[((size_t)m * K_ + k0 + khalf * 4 + i) * DG_ + d] =
            __half_as_ushort(__float2half_rn(ea[i]));
}

// ---------------- main mma.sync kernel: 64 pix x fixed m, 2 CTAs/SM ----------------
#define SM_B1S  0
#define SM_B2S  512
#define SM_I1S  1024
#define SM_SUMS 1536
#define SM_RI   2048
#define SM_SSH  4096                       // S hi (normalized): [64][256] fp16, 528B rows
#define SM_SSL  (4096 + 33792)             // S lo
#define SM_STG  (4096 + 67584)
#define SM_AH   (SM_STG)                   // A chunk hi: [64][16d] 48B rows = 3072
#define SM_AL   (SM_STG + 3072)
#define SM_EH   (SM_STG + 6144)            // E chunk: [256][16d] 48B rows = 12288
#define SM_VH   (SM_STG)                   // V chunk: [128][32k] 80B rows = 10240
#define SM_QB   (SM_STG)                   // qbuf [64][132] f32 = 33792
#define SMEM_TOTAL (4096 + 67584 + 33792)

#define UPD(b1, b2, i1, v, k) do { \
    if ((v) > (b1)) { b2 = b1; b1 = (v); i1 = (k); } \
    else if ((v) > (b2)) b2 = (v); } while (0)

#define LOAD_A(c8) do { _Pragma("unroll") \
    for (int j = 0; j < 2; j++) { \
        int dp = (tid >> 6) + 4 * j, pix = tid & 63; \
        pfA[2 * j]     = latb[(size_t)(16 * (c8) + 2 * dp) * HW_ + pix]; \
        pfA[2 * j + 1] = latb[(size_t)(16 * (c8) + 2 * dp + 1) * HW_ + pix]; \
    } } while (0)
#define LOAD_E(c8) do { _Pragma("unroll") \
    for (int j = 0; j < 2; j++) pfE[j] = ebH[(size_t)tid * 16 + (c8) * 2 + j]; \
    } while (0)
#define STORE_AE() do { _Pragma("unroll") \
    for (int j = 0; j < 2; j++) { \
        int dp = (tid >> 6) + 4 * j, pix = tid & 63; \
        unsigned short h0, l0, h1, l1; \
        fp16_split(pfA[2 * j], h0, l0); fp16_split(pfA[2 * j + 1], h1, l1); \
        *(uint32_t*)(smem + SM_AH + pix * 48 + dp * 4) = ((uint32_t)h1 << 16) | h0; \
        *(uint32_t*)(smem + SM_AL + pix * 48 + dp * 4) = ((uint32_t)l1 << 16) | l0; \
        *(uint4*)(smem + SM_EH + tid * 48 + j * 16) = pfE[j]; \
    } } while (0)
#define LOAD_V(it) do { _Pragma("unroll") \
    for (int jj = 0; jj < 2; jj++) { \
        int q = tid + 256 * jj; \
        pfV[jj] = vtH[(size_t)(q >> 2) * 32 + (it) * 4 + (q & 3)]; \
    } } while (0)
#define STORE_V() do { _Pragma("unroll") \
    for (int jj = 0; jj < 2; jj++) { \
        int q = tid + 256 * jj, dR = q >> 2, kc = q & 3; \
        *(uint4*)(smem + SM_VH + dR * 80 + kc * 16) = pfV[jj]; \
    } } while (0)

__global__ void __launch_bounds__(256, 2)
main_kernel(const float* __restrict__ latent, const float* __restrict__ unif,
            float* __restrict__ quant_out, float* __restrict__ code_out,
            float* __restrict__ logit_out) {
    extern __shared__ char smem[];
    const uint32_t sb = smem_to_u32(smem);
    const int m = blockIdx.y, p0 = blockIdx.x * 64;
    const int n = p0 >> 10, s0 = p0 & 1023;
    const int tid = threadIdx.x, w = tid >> 5, lane = tid & 31;
    const int wp = w >> 1, wk = w & 1;
    const int gid = lane >> 2, tig = lane & 3;
    const int li = lane & 7, lg = lane >> 3;

    float* b1s = (float*)(smem + SM_B1S);
    float* b2s = (float*)(smem + SM_B2S);
    int*   i1s = (int*)(smem + SM_I1S);
    float* sums = (float*)(smem + SM_SUMS);
    float* rinv = (float*)(smem + SM_RI);
    float* qbuf = (float*)(smem + SM_QB);

    const int a_row = wp * 16 + ((lg & 1) << 3) + li;
    const int a_col = ((lg >> 1) << 3);
    const int b_row = ((lg >> 1) << 3) + li;
    const int b_col = ((lg & 1) << 3);
    const uint32_t aAh = sb + SM_AH + a_row * 48 + a_col * 2;
    const uint32_t aAl = sb + SM_AL + a_row * 48 + a_col * 2;
    const uint32_t aEh = sb + SM_EH + (wk * 128 + b_row) * 48 + b_col * 2;

    const float* latb = latent + ((size_t)n * D_ + (size_t)m * DG_) * HW_ + s0;
    const uint4* ebH = (const uint4*)(g_Eh + (size_t)m * K_ * DG_);
    const uint4* vtH = (const uint4*)(g_Vh + (size_t)m * DG_ * K_);

    // ================= GEMM1: logits[64 pix][256 k] =================
    float acc[16][4];
#pragma unroll
    for (int i = 0; i < 16; i++)
#pragma unroll
        for (int j = 0; j < 4; j++) acc[i][j] = 0.f;

    float pfA[4];
    uint4 pfE[2];
    LOAD_A(0); LOAD_E(0);

    for (int c8 = 0; c8 < 8; c8++) {
        STORE_AE();
        __syncthreads();
        if (c8 < 7) { LOAD_A(c8 + 1); LOAD_E(c8 + 1); }
        uint32_t ah[4], al[4];
        ldsm4(ah, aAh);
        ldsm4(al, aAl);
#pragma unroll
        for (int nf2 = 0; nf2 < 8; nf2++) {
            uint32_t bh[4];
            ldsm4(bh, aEh + nf2 * 768);
            mma_f16(acc[2 * nf2], ah, bh);
            mma_f16(acc[2 * nf2], al, bh);
            mma_f16(acc[2 * nf2 + 1], ah, bh + 2);
            mma_f16(acc[2 * nf2 + 1], al, bh + 2);
        }
        __syncthreads();
    }

    // ================= Epilogue pass 1: logits out, top-2, e -> acc =================
    const int p_r = wp * 16 + gid;
    const size_t pgA = (size_t)(p0 + p_r), pgB = pgA + 8;
    float* lpA = logit_out + (pgA * M_ + m) * K_ + wk * 128 + 2 * tig;
    float* lpB = logit_out + (pgB * M_ + m) * K_ + wk * 128 + 2 * tig;
    const float* upA = unif + (pgA * M_ + m) * K_ + wk * 128 + 2 * tig;
    const float* upB = unif + (pgB * M_ + m) * K_ + wk * 128 + 2 * tig;

    float b1r[2] = {-3.4e38f, -3.4e38f}, b2r[2] = {-3.4e38f, -3.4e38f};
    int i1r[2] = {0, 0};
    float sumr[2] = {0.f, 0.f};

#pragma unroll
    for (int nf = 0; nf < 16; nf++) {
        int kk = wk * 128 + nf * 8 + 2 * tig;
        float l00 = acc[nf][0], l01 = acc[nf][1], l10 = acc[nf][2], l11 = acc[nf][3];
        *(float2*)(lpA + nf * 8) = make_float2(l00, l01);
        *(float2*)(lpB + nf * 8) = make_float2(l10, l11);
        float2 u0 = *(const float2*)(upA + nf * 8);
        float2 u1 = *(const float2*)(upB + nf * 8);
        UPD(b1r[0], b2r[0], i1r[0], l00, kk);
        UPD(b1r[0], b2r[0], i1r[0], l01, kk + 1);
        UPD(b1r[1], b2r[1], i1r[1], l10, kk);
        UPD(b1r[1], b2r[1], i1r[1], l11, kk + 1);
        float e00 = __fdividef(__expf(l00), neglog_acc(u0.x));
        float e01 = __fdividef(__expf(l01), neglog_acc(u0.y));
        float e10 = __fdividef(__expf(l10), neglog_acc(u1.x));
        float e11 = __fdividef(__expf(l11), neglog_acc(u1.y));
        sumr[0] += e00 + e01;
        sumr[1] += e10 + e11;
        acc[nf][0] = e00; acc[nf][1] = e01; acc[nf][2] = e10; acc[nf][3] = e11;
    }

    uint4 pfV[2];
    LOAD_V(0);

#pragma unroll
    for (int r = 0; r < 2; r++) {
#pragma unroll
        for (int o = 1; o <= 2; o <<= 1) {
            float ob1 = __shfl_xor_sync(0xFFFFFFFFu, b1r[r], o);
            int   oi1 = __shfl_xor_sync(0xFFFFFFFFu, i1r[r], o);
            float ob2 = __shfl_xor_sync(0xFFFFFFFFu, b2r[r], o);
            if (ob1 > b1r[r] || (ob1 == b1r[r] && oi1 < i1r[r])) {
                b2r[r] = fmaxf(b1r[r], ob2); b1r[r] = ob1; i1r[r] = oi1;
            } else b2r[r] = fmaxf(b2r[r], ob1);
            sumr[r] += __shfl_xor_sync(0xFFFFFFFFu, sumr[r], o);
        }
    }
    if (tig == 0) {
        b1s[wk * 64 + p_r] = b1r[0];  b1s[wk * 64 + p_r + 8] = b1r[1];
        b2s[wk * 64 + p_r] = b2r[0];  b2s[wk * 64 + p_r + 8] = b2r[1];
        i1s[wk * 64 + p_r] = i1r[0];  i1s[wk * 64 + p_r + 8] = i1r[1];
        sums[wk * 64 + p_r] = sumr[0]; sums[wk * 64 + p_r + 8] = sumr[1];
    }
    __syncthreads();

    if (tid < 64) {
        const int p = tid;
        const size_t pg = (size_t)(p0 + p);
        float a1 = b1s[p], a2 = b2s[p];           int ai = i1s[p];
        float c1 = b1s[64 + p], c2 = b2s[64 + p]; int ci = i1s[64 + p];
        float b1, b2; int i1;
        if (a1 >= c1) { b1 = a1; i1 = ai; b2 = fmaxf(a2, fmaxf(c1, c2)); }
        else          { b1 = c1; i1 = ci; b2 = fmaxf(c2, fmaxf(a1, a2)); }
        rinv[p] = 1.0f / (sums[p] + sums[64 + p]);
        code_out[pg * M_ + m] = (float)i1;
        if (b1 - b2 < GAP_THRESH) {
            int idx = atomicAdd(&g_count, 1);
            if (idx < CAP_) g_list[idx] = (int)(pg * M_ + m);
        }
    }
    __syncthreads();

    // ================= Epilogue pass 2: normalize S, fp16 split -> smem =================
    {
        const float riA = rinv[p_r], riB = rinv[p_r + 8];
#pragma unroll
        for (int nf = 0; nf < 16; nf++) {
            int kk = wk * 128 + nf * 8 + 2 * tig;
            float e00 = acc[nf][0] * riA, e01 = acc[nf][1] * riA;
            float e10 = acc[nf][2] * riB, e11 = acc[nf][3] * riB;
            unsigned short h00, lo00, h01, lo01, h10, lo10, h11, lo11;
            fp16_split(e00, h00, lo00); fp16_split(e01, h01, lo01);
            fp16_split(e10, h10, lo10); fp16_split(e11, h11, lo11);
            *(uint32_t*)(smem + SM_SSH + p_r * 528 + kk * 2)       = ((uint32_t)h01 << 16) | h00;
            *(uint32_t*)(smem + SM_SSH + (p_r + 8) * 528 + kk * 2) = ((uint32_t)h11 << 16) | h10;
            *(uint32_t*)(smem + SM_SSL + p_r * 528 + kk * 2)       = ((uint32_t)lo01 << 16) | lo00;
            *(uint32_t*)(smem + SM_SSL + (p_r + 8) * 528 + kk * 2) = ((uint32_t)lo11 << 16) | lo10;
        }
    }

    // ================= GEMM2: quant[64 pix][128 d] = S_norm x Vt^T =================
    float acc2[8][4];
#pragma unroll
    for (int i = 0; i < 8; i++)
#pragma unroll
        for (int j = 0; j < 4; j++) acc2[i][j] = 0.f;

    const uint32_t aSh = sb + SM_SSH + a_row * 528 + a_col * 2;
    const uint32_t aSl = sb + SM_SSL + a_row * 528 + a_col * 2;
    const uint32_t bvh = sb + SM_VH + (wk * 64 + b_row) * 80 + b_col * 2;

    for (int it = 0; it < 8; it++) {
        STORE_V();
        __syncthreads();
        if (it < 7) LOAD_V(it + 1);
#pragma unroll
        for (int s = 0; s < 2; s++) {
            const int k0 = it * 32 + s * 16;
            uint32_t sh[4], sl[4];
            ldsm4(sh, aSh + k0 * 2);
            ldsm4(sl, aSl + k0 * 2);
#pragma unroll
            for (int nf2 = 0; nf2 < 4; nf2++) {
                uint32_t bh[4];
                ldsm4(bh, bvh + nf2 * 1280 + s * 32);
                mma_f16(acc2[2 * nf2], sh, bh);
                mma_f16(acc2[2 * nf2], sl, bh);
                mma_f16(acc2[2 * nf2 + 1], sh, bh + 2);
                mma_f16(acc2[2 * nf2 + 1], sl, bh + 2);
            }
        }
        __syncthreads();
    }

#pragma unroll
    for (int nf = 0; nf < 8; nf++) {
        int d = wk * 64 + 8 * nf + 2 * tig;
        qbuf[p_r * 132 + d]       = acc2[nf][0];
        qbuf[p_r * 132 + d + 1]   = acc2[nf][1];
        qbuf[(p_r + 8) * 132 + d]     = acc2[nf][2];
        qbuf[(p_r + 8) * 132 + d + 1] = acc2[nf][3];
    }
    __syncthreads();
    {
        const int pix = tid & 63, dg2 = tid >> 6;
        float* qb = quant_out + ((size_t)n * D_ + (size_t)m * DG_) * HW_ + s0 + pix;
#pragma unroll
        for (int j = 0; j < 32; j++) {
            int d = dg2 * 32 + j;
            qb[(size_t)d * HW_] = qbuf[pix * 132 + d];
        }
    }
}

// ---------------- refine: dd-exact argmax for near-tie pixels ----------------
__global__ void __launch_bounds__(128)
refine_kernel(const float* __restrict__ latent, const float* __restrict__ wq,
              const float* __restrict__ logit_out, float* __restrict__ code_out) {
    __shared__ float qv_s[4][DG_], qh_s[4][DG_], ql_s[4][DG_];
    const int wid = threadIdx.x >> 5, lane = threadIdx.x & 31;
    const int gw = blockIdx.x * 4 + wid, tw = gridDim.x * 4;
    int cnt = g_count; if (cnt > CAP_) cnt = CAP_;
    for (int e = gw; e < cnt; e += tw) {
        int ent = g_list[e], m = ent & 7, pg = ent >> 3;
        int n = pg >> 10, s = pg & 1023;
        const float* latb = latent + ((size_t)n * D_ + (size_t)m * DG_) * HW_ + s;
        for (int d = lane; d < DG_; d += 32) qv_s[wid][d] = latb[(size_t)d * HW_];
        __syncwarp();
        const float* wqm = wq + (size_t)m * DG_ * DG_;
#pragma unroll
        for (int ci = 0; ci < 4; ci++) {
            int c = lane + 32 * ci;
            const float* wr = wqm + (size_t)c * DG_;
            dd a; a.h = a.l = 0.f;
            for (int d = 0; d < DG_; d++) a = dd_fma(a, qv_s[wid][d], wr[d]);
            qh_s[wid][c] = a.h; ql_s[wid][c] = a.l;
        }
        __syncwarp();
        const float* lo = logit_out + ((size_t)pg * M_ + m) * K_;
        float l[8], fm = -3.4e38f;
#pragma unroll
        for (int j = 0; j < 8; j++) { l[j] = lo[lane * 8 + j]; fm = fmaxf(fm, l[j]); }
#pragma unroll
        for (int o = 16; o > 0; o >>= 1) fm = fmaxf(fm, __shfl_xor_sync(0xFFFFFFFFu, fm, o));
        float thresh = fm - REF_WIN;
        double bestv = -1e300; int besti = 1 << 30;
        const float* kph = g_KPH + ((size_t)m * K_) * DG_;
        const float* kpl = g_KPL + ((size_t)m * K_) * DG_;
#pragma unroll
        for (int j = 0; j < 8; j++) {
            unsigned b = __ballot_sync(0xFFFFFFFFu, l[j] >= thresh);
            while (b) {
                int src = __ffs(b) - 1; b &= b - 1;
                int k = src * 8 + j;
                const float* kh = kph + (size_t)k * DG_;
                const float* kl = kpl + (size_t)k * DG_;
                dd a; a.h = a.l = 0.f;
#pragma unroll
                for (int ci = 0; ci < 4; ci++) {
                    int c = lane + 32 * ci;
                    dd kp; kp.h = kh[c]; kp.l = kl[c];
                    dd qp; qp.h = qh_s[wid][c]; qp.l = ql_s[wid][c];
                    a = dd_add(a, dd_mul(kp, qp));
                }
                double v = (double)a.h + (double)a.l;
#pragma unroll
                for (int o = 16; o > 0; o >>= 1) v += __shfl_xor_sync(0xFFFFFFFFu, v, o);
                if (v > bestv || (v == bestv && k < besti)) { bestv = v; besti = k; }
            }
        }
        if (lane == 0) code_out[(size_t)pg * M_ + m] = (float)besti;
    }
}

extern "C" void kernel_launch(void* const* d_in, const int* in_sizes, int n_in,
                              void* d_out, int out_size) {
    const float* latent   = (const float*)d_in[0];
    const float* codebook = (const float*)d_in[1];
    const float* wq       = (const float*)d_in[2];
    const float* wk       = (const float*)d_in[3];
    const float* wv       = (const float*)d_in[4];
    const float* unif     = (const float*)d_in[5];
    float* out   = (float*)d_out;
    float* quant = out;
    float* code  = out + QUANT_ELEMS;
    float* logit = out + QUANT_ELEMS + CODE_ELEMS;

    precompute_kernel<<<dim3(K_ / 8, M_), 256>>>(codebook, wq, wk, wv);
    cudaFuncSetAttribute(main_kernel, cudaFuncAttributeMaxDynamicSharedMemorySize, SMEM_TOTAL);
    main_kernel<<<dim3(NPIX_ / 64, M_), 256, SMEM_TOTAL>>>(latent, unif, quant, code, logit);
    refine_kernel<<<128, 128>>>(latent, wq, logit, code);
}